// round 8
// baseline (speedup 1.0000x reference)
#include <cuda_runtime.h>
#include <cuda_bf16.h>
#include <cstdint>
#include <cstddef>

#define B_DIM 32
#define HDIM  512
#define NDIM  4096
#define MDIM  128
#define TDIM  256

// __device__ scratch (allocation-free rule). Wp as bf16 hi/lo, two layouts.
__device__ __align__(16) __nv_bfloat16 g_WpT_hi[B_DIM * MDIM * HDIM]; // [b][m][h]
__device__ __align__(16) __nv_bfloat16 g_WpT_lo[B_DIM * MDIM * HDIM];
__device__ __align__(16) __nv_bfloat16 g_Wp_hi [B_DIM * HDIM * MDIM]; // [b][h][m]
__device__ __align__(16) __nv_bfloat16 g_Wp_lo [B_DIM * HDIM * MDIM];

// ---------------- helpers (all non-arch-specific PTX) ----------------
__device__ __forceinline__ uint32_t smem_u32(const void* p) {
    uint32_t a;
    asm("{ .reg .u64 t; cvta.to.shared.u64 t, %1; cvt.u32.u64 %0, t; }"
        : "=r"(a) : "l"(p));
    return a;
}
__device__ __forceinline__ void ldsm4(uint32_t* r, uint32_t a) {
    asm volatile("ldmatrix.sync.aligned.m8n8.x4.shared.b16 {%0,%1,%2,%3}, [%4];"
        : "=r"(r[0]), "=r"(r[1]), "=r"(r[2]), "=r"(r[3]) : "r"(a));
}
__device__ __forceinline__ void ldsm4t(uint32_t* r, uint32_t a) {
    asm volatile("ldmatrix.sync.aligned.m8n8.x4.trans.shared.b16 {%0,%1,%2,%3}, [%4];"
        : "=r"(r[0]), "=r"(r[1]), "=r"(r[2]), "=r"(r[3]) : "r"(a));
}
__device__ __forceinline__ void mma16816(float* d, const uint32_t* a,
                                         uint32_t b0, uint32_t b1) {
    asm volatile(
        "mma.sync.aligned.m16n8k16.row.col.f32.bf16.bf16.f32 "
        "{%0,%1,%2,%3}, {%4,%5,%6,%7}, {%8,%9}, {%0,%1,%2,%3};"
        : "+f"(d[0]), "+f"(d[1]), "+f"(d[2]), "+f"(d[3])
        : "r"(a[0]), "r"(a[1]), "r"(a[2]), "r"(a[3]), "r"(b0), "r"(b1));
}
__device__ __forceinline__ void split2(float x, float y, uint32_t& hi, uint32_t& lo) {
    __nv_bfloat16 xh = __float2bfloat16(x);
    __nv_bfloat16 yh = __float2bfloat16(y);
    __nv_bfloat16 xl = __float2bfloat16(x - __bfloat162float(xh));
    __nv_bfloat16 yl = __float2bfloat16(y - __bfloat162float(yh));
    hi = (uint32_t)__bfloat16_as_ushort(xh) | ((uint32_t)__bfloat16_as_ushort(yh) << 16);
    lo = (uint32_t)__bfloat16_as_ushort(xl) | ((uint32_t)__bfloat16_as_ushort(yl) << 16);
}
#define CP_ASYNC16(dst, src)                                                   \
    asm volatile("cp.async.cg.shared.global [%0], [%1], 16;"                   \
                 :: "r"(dst), "l"(src))
#define CP_COMMIT() asm volatile("cp.async.commit_group;" ::: "memory")
#define CP_WAIT(n)  asm volatile("cp.async.wait_group %0;" :: "n"(n) : "memory")

// ============================================================
// Kernel 1: Wp[b,h,m] = sum_t head_w[h,t] * W[b,t,m] (fp32 scalar),
// written as bf16 hi/lo splits in [h][m] and [m][h] layouts.
// Grid (16, 32): tile 32h x 128m, 256 threads, per-thread 2h x 8m.
// ============================================================
__global__ __launch_bounds__(256) void proj_kernel(const float* __restrict__ W,
                                                   const float* __restrict__ head_w) {
    __shared__ float sA[32][33];   // sA[t][h]  (32 h per tile)
    __shared__ float sB[32][128];  // sB[t][m]
    const int tid = threadIdx.x;
    const int b   = blockIdx.y;
    const int h0  = blockIdx.x * 32;
    const int tx  = tid & 15, ty = tid >> 4;

    float acc[2][8];
#pragma unroll
    for (int i = 0; i < 2; i++)
#pragma unroll
        for (int j = 0; j < 8; j++) acc[i][j] = 0.f;

    const float* Wb = W + (size_t)b * TDIM * MDIM;
    for (int t0 = 0; t0 < TDIM; t0 += 32) {
        {   // head_w[h0+r][t0+c4..+3] -> sA[t][r]
            int r = tid & 31, c4 = (tid >> 5) << 2;
            float4 v = *(const float4*)(head_w + (size_t)(h0 + r) * TDIM + t0 + c4);
            sA[c4 + 0][r] = v.x; sA[c4 + 1][r] = v.y;
            sA[c4 + 2][r] = v.z; sA[c4 + 3][r] = v.w;
        }
        {   // W[b][t0+r][*] -> sB[r][*]
            int r = tid >> 3, part = tid & 7;
            const float4* src = (const float4*)(Wb + (size_t)(t0 + r) * MDIM + part * 16);
            float4* dst = (float4*)(&sB[r][part * 16]);
#pragma unroll
            for (int i = 0; i < 4; i++) dst[i] = src[i];
        }
        __syncthreads();
#pragma unroll
        for (int t = 0; t < 32; t++) {
            float a0 = sA[t][ty * 2], a1 = sA[t][ty * 2 + 1];
            float bb[8];
#pragma unroll
            for (int j = 0; j < 8; j++) bb[j] = sB[t][tx * 8 + j];
#pragma unroll
            for (int j = 0; j < 8; j++) {
                acc[0][j] = fmaf(a0, bb[j], acc[0][j]);
                acc[1][j] = fmaf(a1, bb[j], acc[1][j]);
            }
        }
        __syncthreads();
    }
#pragma unroll
    for (int i = 0; i < 2; i++) {
        int h = h0 + ty * 2 + i;
#pragma unroll
        for (int j = 0; j < 8; j++) {
            int m = tx * 8 + j;
            float v = acc[i][j];
            __nv_bfloat16 hi = __float2bfloat16(v);
            __nv_bfloat16 lo = __float2bfloat16(v - __bfloat162float(hi));
            size_t pidx = ((size_t)b * HDIM + h) * MDIM + m;
            g_Wp_hi[pidx] = hi;  g_Wp_lo[pidx] = lo;
            size_t tidx = ((size_t)b * MDIM + m) * HDIM + h;
            g_WpT_hi[tidx] = hi; g_WpT_lo[tidx] = lo;
        }
    }
}

// ============================================================
// Kernel 2: fused scores -> softmax -> output.
// CTA = (batch b, 64-row n-tile), 128 threads = 4 warps x 16 n-rows.
// 2 CTAs per SM. One barrier per GEMM1 chunk (Q double-buffered,
// convert runs between sync and MMA); B-fragment LDSM pipelined.
//
// SMEM union (bytes):
//   GEMM1: KB0 @0 (36864 = hi 18432 + lo 18432), KB1 @36864 (end 73728),
//          Q0 @73728 (hi 9216 + lo 9216), Q1 @92160  -> end 110592
//   GEMM2: WB0 @0 (34816 = hi 17408 + lo 17408), WB1 @34816 (end 69632),
//          STG0 @69632 (17408), STG1 @87040          -> end 104448
// ============================================================
#define PADQ 72      // Q tile [k=64][n=64] bf16 row stride
#define PADK 72      // K tile [m=128][k=64] bf16 row stride
#define PADW 136     // W tile [h=64][m=128] bf16 row stride
#define STGS 68      // out stage [h=64][n=64] fp32 row stride
#define OFF_KB  0
#define KB_SZ   36864
#define OFF_Q   73728
#define Q_SZ    18432
#define OFF_WB  0
#define WB_SZ   34816
#define OFF_STG 69632
#define STG_SZ  17408
#define SMEM_DYN 110592

__global__ __launch_bounds__(128, 2)
void attn_kernel(const float* __restrict__ H, float* __restrict__ out) {
    extern __shared__ char smem[];
    const uint32_t sbase = smem_u32(smem);

    const int tid = threadIdx.x;
    const int wid = tid >> 5;
    const int lid = tid & 31;
    const int b   = blockIdx.y;
    const int n0  = blockIdx.x * 64;

    const float* Hb = H + (size_t)b * HDIM * NDIM + n0;
    const __nv_bfloat16* KTh = g_WpT_hi + (size_t)b * MDIM * HDIM;
    const __nv_bfloat16* KTl = g_WpT_lo + (size_t)b * MDIM * HDIM;
    const __nv_bfloat16* Wph = g_Wp_hi  + (size_t)b * HDIM * MDIM;
    const __nv_bfloat16* Wpl = g_Wp_lo  + (size_t)b * HDIM * MDIM;

    // per-lane ldmatrix geometry (identical fragment mapping to passing R7)
    const int g  = lid >> 3, lr = lid & 7;
    const int arow = ((g & 2) ? 8 : 0) + lr;                 // + kk*16
    const int acol = wid * 16 + ((g & 1) ? 8 : 0);           // n (0..63)
    const uint32_t a_off = (uint32_t)(arow * PADQ + acol) * 2;
    const int brow = ((g >> 1) ? 8 : 0) + lr;                // + tp*16
    const int bcol = (g & 1) ? 8 : 0;                        // + kk*16
    const uint32_t b_off_k = (uint32_t)(brow * PADK + bcol) * 2;
    const uint32_t b_off_w = (uint32_t)(brow * PADW + bcol) * 2;

    // ---- async issue helpers ----
    auto issue_k = [&](int hc, int p) {
        uint32_t dh = sbase + OFF_KB + p * KB_SZ;
        uint32_t dl = dh + 18432;
        int k0 = hc * 64;
#pragma unroll
        for (int it = 0; it < 8; it++) {
            int f = it * 128 + tid, m = f >> 3, c8 = (f & 7) << 3;
            uint32_t o = (uint32_t)(m * PADK + c8) * 2;
            CP_ASYNC16(dh + o, KTh + (size_t)m * HDIM + k0 + c8);
            CP_ASYNC16(dl + o, KTl + (size_t)m * HDIM + k0 + c8);
        }
    };
    auto issue_w = [&](int hc2, int p) {
        uint32_t dh = sbase + OFF_WB + p * WB_SZ;
        uint32_t dl = dh + 17408;
#pragma unroll
        for (int it = 0; it < 8; it++) {
            int f = it * 128 + tid, hr = f >> 4, c8 = (f & 15) << 3;
            uint32_t o = (uint32_t)(hr * PADW + c8) * 2;
            CP_ASYNC16(dh + o, Wph + (size_t)(hc2 * 64 + hr) * MDIM + c8);
            CP_ASYNC16(dl + o, Wpl + (size_t)(hc2 * 64 + hr) * MDIM + c8);
        }
    };
    // Q chunk -> registers (8 float4/thread: rows hr=f>>4, cols (f&15)*4)
    auto ldg_q = [&](int hc, float4* qv) {
#pragma unroll
        for (int it = 0; it < 8; it++) {
            int f = it * 128 + tid, hr = f >> 4, c4 = (f & 15) << 2;
            qv[it] = *(const float4*)(Hb + (size_t)(hc * 64 + hr) * NDIM + c4);
        }
    };
    // convert registers -> Q buffer q (bf16 hi/lo split)
    auto conv_q = [&](const float4* qv, int q) {
        uint32_t base_h = OFF_Q + q * Q_SZ;
#pragma unroll
        for (int it = 0; it < 8; it++) {
            int f = it * 128 + tid, hr = f >> 4, c4 = (f & 15) << 2;
            uint32_t h01, l01, h23, l23;
            split2(qv[it].x, qv[it].y, h01, l01);
            split2(qv[it].z, qv[it].w, h23, l23);
            uint32_t off = (uint32_t)(hr * PADQ + c4) * 2;
            *(uint2*)(smem + base_h + off)        = make_uint2(h01, h23);
            *(uint2*)(smem + base_h + 9216 + off) = make_uint2(l01, l23);
        }
    };

    // ---------------- GEMM1: S[n][m] = sum_h Q[n][h] * WpT[m][h] ----------------
    float sacc[16][4];
#pragma unroll
    for (int t = 0; t < 16; t++)
#pragma unroll
        for (int j = 0; j < 4; j++) sacc[t][j] = 0.f;

    float4 qv[8];
    issue_k(0, 0); CP_COMMIT();
    ldg_q(0, qv);
    conv_q(qv, 0);              // chunk 0 -> Q buffer 0
    ldg_q(1, qv);

    for (int hc = 0; hc < 8; hc++) {
        const int p = hc & 1;
        CP_WAIT(0);
        __syncthreads();                 // K[p] + Q[p] visible to all warps
        if (hc < 7) {
            issue_k(hc + 1, p ^ 1); CP_COMMIT();
            conv_q(qv, p ^ 1);           // chunk hc+1 -> Q[p^1] (visible next sync)
        }
        if (hc < 6) ldg_q(hc + 2, qv);

        const uint32_t qhi = sbase + OFF_Q + p * Q_SZ;
        const uint32_t qlo = qhi + 9216;
        const uint32_t khi = sbase + OFF_KB + p * KB_SZ;
        const uint32_t klo = khi + 18432;
#pragma unroll
        for (int kk = 0; kk < 4; kk++) {
            uint32_t ah[4], al[4];
            uint32_t aoff = a_off + (uint32_t)(kk * 16 * PADQ) * 2;
            ldsm4t(ah, qhi + aoff);
            ldsm4t(al, qlo + aoff);
            uint32_t bh0[4], bl0[4], bh1[4], bl1[4];
            {
                uint32_t boff = b_off_k + (uint32_t)(kk * 16) * 2;
                ldsm4(bh0, khi + boff);
                ldsm4(bl0, klo + boff);
            }
#pragma unroll
            for (int tp = 0; tp < 8; tp++) {
                uint32_t* bh = (tp & 1) ? bh1 : bh0;
                uint32_t* bl = (tp & 1) ? bl1 : bl0;
                if (tp < 7) {
                    uint32_t* nbh = (tp & 1) ? bh0 : bh1;
                    uint32_t* nbl = (tp & 1) ? bl0 : bl1;
                    uint32_t boff =
                        b_off_k + (uint32_t)((tp + 1) * 16 * PADK + kk * 16) * 2;
                    ldsm4(nbh, khi + boff);
                    ldsm4(nbl, klo + boff);
                }
                mma16816(sacc[2 * tp],     ah, bh[0], bh[1]);
                mma16816(sacc[2 * tp],     ah, bl[0], bl[1]);
                mma16816(sacc[2 * tp],     al, bh[0], bh[1]);
                mma16816(sacc[2 * tp + 1], ah, bh[2], bh[3]);
                mma16816(sacc[2 * tp + 1], ah, bl[2], bl[3]);
                mma16816(sacc[2 * tp + 1], al, bh[2], bh[3]);
            }
        }
        // no end barrier: KB[p^1]/Q[p^1] writes are gated by the next top-sync
    }

    // prefetch GEMM2 chunk 0 (WB0 @0..34816 doesn't overlap KB1/Q1 still in use)
    issue_w(0, 0); CP_COMMIT();

    // ---------------- softmax over m (registers only) ----------------
    float mx0 = -3.4e38f, mx1 = -3.4e38f;
#pragma unroll
    for (int t = 0; t < 16; t++) {
        mx0 = fmaxf(mx0, fmaxf(sacc[t][0], sacc[t][1]));
        mx1 = fmaxf(mx1, fmaxf(sacc[t][2], sacc[t][3]));
    }
    mx0 = fmaxf(mx0, __shfl_xor_sync(0xFFFFFFFFu, mx0, 1));
    mx0 = fmaxf(mx0, __shfl_xor_sync(0xFFFFFFFFu, mx0, 2));
    mx1 = fmaxf(mx1, __shfl_xor_sync(0xFFFFFFFFu, mx1, 1));
    mx1 = fmaxf(mx1, __shfl_xor_sync(0xFFFFFFFFu, mx1, 2));
    float s0 = 0.f, s1 = 0.f;
#pragma unroll
    for (int t = 0; t < 16; t++) {
        sacc[t][0] = __expf(sacc[t][0] - mx0);
        sacc[t][1] = __expf(sacc[t][1] - mx0);
        sacc[t][2] = __expf(sacc[t][2] - mx1);
        sacc[t][3] = __expf(sacc[t][3] - mx1);
        s0 += sacc[t][0] + sacc[t][1];
        s1 += sacc[t][2] + sacc[t][3];
    }
    s0 += __shfl_xor_sync(0xFFFFFFFFu, s0, 1);
    s0 += __shfl_xor_sync(0xFFFFFFFFu, s0, 2);
    s1 += __shfl_xor_sync(0xFFFFFFFFu, s1, 1);
    s1 += __shfl_xor_sync(0xFFFFFFFFu, s1, 2);
    const float r0 = 1.0f / s0, r1 = 1.0f / s1;

    // Repack unnormalized E into GEMM2 A-fragments (k = m), hi/lo split.
    uint32_t eh[8][4], el[8][4];
#pragma unroll
    for (int kk = 0; kk < 8; kk++) {
        int t0 = kk * 2;
        split2(sacc[t0][0],     sacc[t0][1],     eh[kk][0], el[kk][0]);
        split2(sacc[t0][2],     sacc[t0][3],     eh[kk][1], el[kk][1]);
        split2(sacc[t0 + 1][0], sacc[t0 + 1][1], eh[kk][2], el[kk][2]);
        split2(sacc[t0 + 1][2], sacc[t0 + 1][3], eh[kk][3], el[kk][3]);
    }

    // ---------------- GEMM2: C[n][h] = sum_m E[n][m] * Wp[h][m] ----------------
    float* outb = out + (size_t)b * HDIM * NDIM;
    const int rr = lid >> 2, qq = lid & 3;

    for (int hc2 = 0; hc2 < 8; hc2++) {
        const int p = hc2 & 1;
        CP_WAIT(0);
        __syncthreads();                 // WB[p] visible; STG[p] free
        if (hc2 < 7) { issue_w(hc2 + 1, p ^ 1); CP_COMMIT(); }

        float cacc[8][4];
#pragma unroll
        for (int t = 0; t < 8; t++)
#pragma unroll
            for (int j = 0; j < 4; j++) cacc[t][j] = 0.f;

        const uint32_t whi = sbase + OFF_WB + p * WB_SZ;
        const uint32_t wlo = whi + 17408;
#pragma unroll
        for (int kk = 0; kk < 8; kk++) {
            uint32_t bh0[4], bl0[4], bh1[4], bl1[4];
            {
                uint32_t boff = b_off_w + (uint32_t)(kk * 16) * 2;
                ldsm4(bh0, whi + boff);
                ldsm4(bl0, wlo + boff);
            }
#pragma unroll
            for (int tp = 0; tp < 4; tp++) {
                uint32_t* bh = (tp & 1) ? bh1 : bh0;
                uint32_t* bl = (tp & 1) ? bl1 : bl0;
                if (tp < 3) {
                    uint32_t* nbh = (tp & 1) ? bh0 : bh1;
                    uint32_t* nbl = (tp & 1) ? bl0 : bl1;
                    uint32_t boff =
                        b_off_w + (uint32_t)((tp + 1) * 16 * PADW + kk * 16) * 2;
                    ldsm4(nbh, whi + boff);
                    ldsm4(nbl, wlo + boff);
                }
                mma16816(cacc[2 * tp],     eh[kk], bh[0], bh[1]);
                mma16816(cacc[2 * tp],     eh[kk], bl[0], bl[1]);
                mma16816(cacc[2 * tp],     el[kk], bh[0], bh[1]);
                mma16816(cacc[2 * tp + 1], eh[kk], bh[2], bh[3]);
                mma16816(cacc[2 * tp + 1], eh[kk], bl[2], bl[3]);
                mma16816(cacc[2 * tp + 1], el[kk], bh[2], bh[3]);
            }
        }

        // scale by 1/sum and stage transposed into STG[p]: stg[h_local][n]
        float* stg = (float*)(smem + OFF_STG + p * STG_SZ);
#pragma unroll
        for (int t = 0; t < 8; t++) {
            int hcl = t * 8 + 2 * qq;
            int n   = wid * 16 + rr;
            stg[(size_t)hcl * STGS + n]           = cacc[t][0] * r0;
            stg[(size_t)(hcl + 1) * STGS + n]     = cacc[t][1] * r0;
            stg[(size_t)hcl * STGS + n + 8]       = cacc[t][2] * r1;
            stg[(size_t)(hcl + 1) * STGS + n + 8] = cacc[t][3] * r1;
        }
        __syncthreads();                 // stage writes visible

        // coalesced fp32 store: out[b][hc2*64+hr][n0 + ...]
#pragma unroll
        for (int it = 0; it < 8; it++) {
            int f = it * 128 + tid, hr = f >> 4, n4 = (f & 15) << 2;
            float4 v = *(const float4*)(stg + (size_t)hr * STGS + n4);
            *(float4*)(outb + (size_t)(hc2 * 64 + hr) * NDIM + n0 + n4) = v;
        }
        // no end barrier: STG[p] reused only in hc2+2, after the next top-sync
    }
}

// ============================================================
extern "C" void kernel_launch(void* const* d_in, const int* in_sizes, int n_in,
                              void* d_out, int out_size) {
    const float* H      = (const float*)d_in[0];  // [32,512,64,64]
    const float* W      = (const float*)d_in[1];  // [32,256,128]
    const float* head_w = (const float*)d_in[2];  // [512,256]
    float* out = (float*)d_out;

    cudaFuncSetAttribute(attn_kernel,
                         cudaFuncAttributeMaxDynamicSharedMemorySize, SMEM_DYN);

    proj_kernel<<<dim3(16, B_DIM), 256>>>(W, head_w);
    attn_kernel<<<dim3(NDIM / 64, B_DIM), 128, SMEM_DYN>>>(H, out);
}

// round 9
// speedup vs baseline: 1.1488x; 1.1488x over previous
#include <cuda_runtime.h>
#include <cuda_bf16.h>
#include <cstdint>
#include <cstddef>

#define B_DIM 32
#define HDIM  512
#define NDIM  4096
#define MDIM  128
#define TDIM  256

// __device__ scratch (allocation-free rule). Wp as bf16 hi/lo, two layouts.
__device__ __align__(16) __nv_bfloat16 g_WpT_hi[B_DIM * MDIM * HDIM]; // [b][m][h]
__device__ __align__(16) __nv_bfloat16 g_WpT_lo[B_DIM * MDIM * HDIM];
__device__ __align__(16) __nv_bfloat16 g_Wp_hi [B_DIM * HDIM * MDIM]; // [b][h][m]
__device__ __align__(16) __nv_bfloat16 g_Wp_lo [B_DIM * HDIM * MDIM];

// ---------------- helpers (all non-arch-specific PTX) ----------------
__device__ __forceinline__ uint32_t smem_u32(const void* p) {
    uint32_t a;
    asm("{ .reg .u64 t; cvta.to.shared.u64 t, %1; cvt.u32.u64 %0, t; }"
        : "=r"(a) : "l"(p));
    return a;
}
__device__ __forceinline__ void ldsm4(uint32_t* r, uint32_t a) {
    asm volatile("ldmatrix.sync.aligned.m8n8.x4.shared.b16 {%0,%1,%2,%3}, [%4];"
        : "=r"(r[0]), "=r"(r[1]), "=r"(r[2]), "=r"(r[3]) : "r"(a));
}
__device__ __forceinline__ void ldsm4t(uint32_t* r, uint32_t a) {
    asm volatile("ldmatrix.sync.aligned.m8n8.x4.trans.shared.b16 {%0,%1,%2,%3}, [%4];"
        : "=r"(r[0]), "=r"(r[1]), "=r"(r[2]), "=r"(r[3]) : "r"(a));
}
__device__ __forceinline__ void mma16816(float* d, const uint32_t* a,
                                         uint32_t b0, uint32_t b1) {
    asm volatile(
        "mma.sync.aligned.m16n8k16.row.col.f32.bf16.bf16.f32 "
        "{%0,%1,%2,%3}, {%4,%5,%6,%7}, {%8,%9}, {%0,%1,%2,%3};"
        : "+f"(d[0]), "+f"(d[1]), "+f"(d[2]), "+f"(d[3])
        : "r"(a[0]), "r"(a[1]), "r"(a[2]), "r"(a[3]), "r"(b0), "r"(b1));
}
__device__ __forceinline__ void split2(float x, float y, uint32_t& hi, uint32_t& lo) {
    __nv_bfloat16 xh = __float2bfloat16(x);
    __nv_bfloat16 yh = __float2bfloat16(y);
    __nv_bfloat16 xl = __float2bfloat16(x - __bfloat162float(xh));
    __nv_bfloat16 yl = __float2bfloat16(y - __bfloat162float(yh));
    hi = (uint32_t)__bfloat16_as_ushort(xh) | ((uint32_t)__bfloat16_as_ushort(yh) << 16);
    lo = (uint32_t)__bfloat16_as_ushort(xl) | ((uint32_t)__bfloat16_as_ushort(yl) << 16);
}
#define CP_ASYNC16(dst, src)                                                   \
    asm volatile("cp.async.cg.shared.global [%0], [%1], 16;"                   \
                 :: "r"(dst), "l"(src))
#define CP_COMMIT() asm volatile("cp.async.commit_group;" ::: "memory")
#define CP_WAIT(n)  asm volatile("cp.async.wait_group %0;" :: "n"(n) : "memory")

// ============================================================
// Kernel 1 (reverted to the R7-proven version): Wp = head_w x W.
// Grid (4, 32): tile 128h x 128m, 256 threads, 8x8 register tiles.
// ============================================================
__global__ __launch_bounds__(256) void proj_kernel(const float* __restrict__ W,
                                                   const float* __restrict__ head_w) {
    __shared__ float sA[32][128];  // sA[t][h]
    __shared__ float sB[32][128];  // sB[t][m]
    const int tid = threadIdx.x;
    const int b   = blockIdx.y;
    const int h0  = blockIdx.x * 128;
    const int tx  = tid & 15, ty = tid >> 4;

    float acc[8][8];
#pragma unroll
    for (int i = 0; i < 8; i++)
#pragma unroll
        for (int j = 0; j < 8; j++) acc[i][j] = 0.f;

    const float* Wb = W + (size_t)b * TDIM * MDIM;
    for (int t0 = 0; t0 < TDIM; t0 += 32) {
        {
            int r = tid >> 1, half = tid & 1;
            const float4* src =
                (const float4*)(head_w + (size_t)(h0 + r) * TDIM + t0 + half * 16);
#pragma unroll
            for (int i = 0; i < 4; i++) {
                float4 v = src[i];
                int tt = half * 16 + i * 4;
                sA[tt + 0][r] = v.x; sA[tt + 1][r] = v.y;
                sA[tt + 2][r] = v.z; sA[tt + 3][r] = v.w;
            }
        }
        {
            int r = tid >> 3, part = tid & 7;
            const float4* src = (const float4*)(Wb + (size_t)(t0 + r) * MDIM + part * 16);
            float4* dst = (float4*)(&sB[r][part * 16]);
#pragma unroll
            for (int i = 0; i < 4; i++) dst[i] = src[i];
        }
        __syncthreads();
#pragma unroll
        for (int t = 0; t < 32; t++) {
            float a[8], bb[8];
#pragma unroll
            for (int i = 0; i < 8; i++) a[i] = sA[t][ty * 8 + i];
#pragma unroll
            for (int j = 0; j < 8; j++) bb[j] = sB[t][tx * 8 + j];
#pragma unroll
            for (int i = 0; i < 8; i++)
#pragma unroll
                for (int j = 0; j < 8; j++) acc[i][j] = fmaf(a[i], bb[j], acc[i][j]);
        }
        __syncthreads();
    }
#pragma unroll
    for (int i = 0; i < 8; i++) {
        int h = h0 + ty * 8 + i;
#pragma unroll
        for (int j = 0; j < 8; j++) {
            int m = tx * 8 + j;
            float v = acc[i][j];
            __nv_bfloat16 hi = __float2bfloat16(v);
            __nv_bfloat16 lo = __float2bfloat16(v - __bfloat162float(hi));
            size_t pidx = ((size_t)b * HDIM + h) * MDIM + m;
            g_Wp_hi[pidx] = hi;  g_Wp_lo[pidx] = lo;
            size_t tidx = ((size_t)b * MDIM + m) * HDIM + h;
            g_WpT_hi[tidx] = hi; g_WpT_lo[tidx] = lo;
        }
    }
}

// ============================================================
// Kernel 2: fused scores -> softmax -> output.
// CTA = (batch b, 64-row n-tile), 128 threads = 4 warps x 16 n-rows.
// 2 CTAs per SM. MMAs issued round-robin over 4 independent
// accumulator chains (tp pairs) to break HMMA RAW serialization.
// ============================================================
#define PADQ 72      // Q tile [k=64][n=64] bf16 row stride
#define PADK 72      // K tile [m=128][k=64] bf16 row stride
#define PADW 136     // W tile [h=64][m=128] bf16 row stride
#define STGS 68      // out stage [h=64][n=64] fp32 row stride
#define OFF_KB  0
#define KB_SZ   36864
#define OFF_Q   73728
#define Q_SZ    18432
#define OFF_WB  0
#define WB_SZ   34816
#define OFF_STG 69632
#define STG_SZ  17408
#define SMEM_DYN 110592

__global__ __launch_bounds__(128, 2)
void attn_kernel(const float* __restrict__ H, float* __restrict__ out) {
    extern __shared__ char smem[];
    const uint32_t sbase = smem_u32(smem);

    const int tid = threadIdx.x;
    const int wid = tid >> 5;
    const int lid = tid & 31;
    const int b   = blockIdx.y;
    const int n0  = blockIdx.x * 64;

    const float* Hb = H + (size_t)b * HDIM * NDIM + n0;
    const __nv_bfloat16* KTh = g_WpT_hi + (size_t)b * MDIM * HDIM;
    const __nv_bfloat16* KTl = g_WpT_lo + (size_t)b * MDIM * HDIM;
    const __nv_bfloat16* Wph = g_Wp_hi  + (size_t)b * HDIM * MDIM;
    const __nv_bfloat16* Wpl = g_Wp_lo  + (size_t)b * HDIM * MDIM;

    // per-lane ldmatrix geometry (identical fragment mapping to passing R7/R8)
    const int g  = lid >> 3, lr = lid & 7;
    const int arow = ((g & 2) ? 8 : 0) + lr;                 // + kk*16
    const int acol = wid * 16 + ((g & 1) ? 8 : 0);           // n (0..63)
    const uint32_t a_off = (uint32_t)(arow * PADQ + acol) * 2;
    const int brow = ((g >> 1) ? 8 : 0) + lr;                // + tp*16
    const int bcol = (g & 1) ? 8 : 0;                        // + kk*16
    const uint32_t b_off_k = (uint32_t)(brow * PADK + bcol) * 2;
    const uint32_t b_off_w = (uint32_t)(brow * PADW + bcol) * 2;

    // ---- async issue helpers ----
    auto issue_k = [&](int hc, int p) {
        uint32_t dh = sbase + OFF_KB + p * KB_SZ;
        uint32_t dl = dh + 18432;
        int k0 = hc * 64;
#pragma unroll
        for (int it = 0; it < 8; it++) {
            int f = it * 128 + tid, m = f >> 3, c8 = (f & 7) << 3;
            uint32_t o = (uint32_t)(m * PADK + c8) * 2;
            CP_ASYNC16(dh + o, KTh + (size_t)m * HDIM + k0 + c8);
            CP_ASYNC16(dl + o, KTl + (size_t)m * HDIM + k0 + c8);
        }
    };
    auto issue_w = [&](int hc2, int p) {
        uint32_t dh = sbase + OFF_WB + p * WB_SZ;
        uint32_t dl = dh + 17408;
#pragma unroll
        for (int it = 0; it < 8; it++) {
            int f = it * 128 + tid, hr = f >> 4, c8 = (f & 15) << 3;
            uint32_t o = (uint32_t)(hr * PADW + c8) * 2;
            CP_ASYNC16(dh + o, Wph + (size_t)(hc2 * 64 + hr) * MDIM + c8);
            CP_ASYNC16(dl + o, Wpl + (size_t)(hc2 * 64 + hr) * MDIM + c8);
        }
    };
    auto ldg_q = [&](int hc, float4* qv) {
#pragma unroll
        for (int it = 0; it < 8; it++) {
            int f = it * 128 + tid, hr = f >> 4, c4 = (f & 15) << 2;
            qv[it] = *(const float4*)(Hb + (size_t)(hc * 64 + hr) * NDIM + c4);
        }
    };
    auto conv_q = [&](const float4* qv, int q) {
        uint32_t base_h = OFF_Q + q * Q_SZ;
#pragma unroll
        for (int it = 0; it < 8; it++) {
            int f = it * 128 + tid, hr = f >> 4, c4 = (f & 15) << 2;
            uint32_t h01, l01, h23, l23;
            split2(qv[it].x, qv[it].y, h01, l01);
            split2(qv[it].z, qv[it].w, h23, l23);
            uint32_t off = (uint32_t)(hr * PADQ + c4) * 2;
            *(uint2*)(smem + base_h + off)        = make_uint2(h01, h23);
            *(uint2*)(smem + base_h + 9216 + off) = make_uint2(l01, l23);
        }
    };

    // ---------------- GEMM1: S[n][m] = sum_h Q[n][h] * WpT[m][h] ----------------
    float sacc[16][4];
#pragma unroll
    for (int t = 0; t < 16; t++)
#pragma unroll
        for (int j = 0; j < 4; j++) sacc[t][j] = 0.f;

    float4 qv[8];
    issue_k(0, 0); CP_COMMIT();
    ldg_q(0, qv);
    conv_q(qv, 0);
    ldg_q(1, qv);

    for (int hc = 0; hc < 8; hc++) {
        const int p = hc & 1;
        CP_WAIT(0);
        __syncthreads();                 // K[p] + Q[p] visible to all warps
        if (hc < 7) {
            issue_k(hc + 1, p ^ 1); CP_COMMIT();
            conv_q(qv, p ^ 1);
        }
        if (hc < 6) ldg_q(hc + 2, qv);

        const uint32_t qhi = sbase + OFF_Q + p * Q_SZ;
        const uint32_t qlo = qhi + 9216;
        const uint32_t khi = sbase + OFF_KB + p * KB_SZ;
        const uint32_t klo = khi + 18432;
#pragma unroll
        for (int kk = 0; kk < 4; kk++) {
            uint32_t ah[4], al[4];
            uint32_t aoff = a_off + (uint32_t)(kk * 16 * PADQ) * 2;
            ldsm4t(ah, qhi + aoff);
            ldsm4t(al, qlo + aoff);
#pragma unroll
            for (int pr = 0; pr < 4; pr++) {         // tp pair (2pr, 2pr+1)
                uint32_t bh0[4], bl0[4], bh1[4], bl1[4];
                uint32_t bo0 = b_off_k + (uint32_t)((2 * pr) * 16 * PADK + kk * 16) * 2;
                uint32_t bo1 = b_off_k + (uint32_t)((2 * pr + 1) * 16 * PADK + kk * 16) * 2;
                ldsm4(bh0, khi + bo0);
                ldsm4(bh1, khi + bo1);
                ldsm4(bl0, klo + bo0);
                ldsm4(bl1, klo + bo1);
                float* A0 = sacc[4 * pr + 0];
                float* A1 = sacc[4 * pr + 1];
                float* A2 = sacc[4 * pr + 2];
                float* A3 = sacc[4 * pr + 3];
                // round-robin over 4 independent accumulator chains;
                // per-acc order hh -> hl -> lh (bit-identical to R7/R8)
                mma16816(A0, ah, bh0[0], bh0[1]);
                mma16816(A1, ah, bh0[2], bh0[3]);
                mma16816(A2, ah, bh1[0], bh1[1]);
                mma16816(A3, ah, bh1[2], bh1[3]);
                mma16816(A0, ah, bl0[0], bl0[1]);
                mma16816(A1, ah, bl0[2], bl0[3]);
                mma16816(A2, ah, bl1[0], bl1[1]);
                mma16816(A3, ah, bl1[2], bl1[3]);
                mma16816(A0, al, bh0[0], bh0[1]);
                mma16816(A1, al, bh0[2], bh0[3]);
                mma16816(A2, al, bh1[0], bh1[1]);
                mma16816(A3, al, bh1[2], bh1[3]);
            }
        }
    }

    // prefetch GEMM2 chunk 0 (WB0 doesn't overlap KB1/Q1 still in use)
    issue_w(0, 0); CP_COMMIT();

    // ---------------- softmax over m (registers only) ----------------
    float mx0 = -3.4e38f, mx1 = -3.4e38f;
#pragma unroll
    for (int t = 0; t < 16; t++) {
        mx0 = fmaxf(mx0, fmaxf(sacc[t][0], sacc[t][1]));
        mx1 = fmaxf(mx1, fmaxf(sacc[t][2], sacc[t][3]));
    }
    mx0 = fmaxf(mx0, __shfl_xor_sync(0xFFFFFFFFu, mx0, 1));
    mx0 = fmaxf(mx0, __shfl_xor_sync(0xFFFFFFFFu, mx0, 2));
    mx1 = fmaxf(mx1, __shfl_xor_sync(0xFFFFFFFFu, mx1, 1));
    mx1 = fmaxf(mx1, __shfl_xor_sync(0xFFFFFFFFu, mx1, 2));
    float s0 = 0.f, s1 = 0.f;
#pragma unroll
    for (int t = 0; t < 16; t++) {
        sacc[t][0] = __expf(sacc[t][0] - mx0);
        sacc[t][1] = __expf(sacc[t][1] - mx0);
        sacc[t][2] = __expf(sacc[t][2] - mx1);
        sacc[t][3] = __expf(sacc[t][3] - mx1);
        s0 += sacc[t][0] + sacc[t][1];
        s1 += sacc[t][2] + sacc[t][3];
    }
    s0 += __shfl_xor_sync(0xFFFFFFFFu, s0, 1);
    s0 += __shfl_xor_sync(0xFFFFFFFFu, s0, 2);
    s1 += __shfl_xor_sync(0xFFFFFFFFu, s1, 1);
    s1 += __shfl_xor_sync(0xFFFFFFFFu, s1, 2);
    const float r0 = 1.0f / s0, r1 = 1.0f / s1;

    // Repack unnormalized E into GEMM2 A-fragments (k = m), hi/lo split.
    uint32_t eh[8][4], el[8][4];
#pragma unroll
    for (int kk = 0; kk < 8; kk++) {
        int t0 = kk * 2;
        split2(sacc[t0][0],     sacc[t0][1],     eh[kk][0], el[kk][0]);
        split2(sacc[t0][2],     sacc[t0][3],     eh[kk][1], el[kk][1]);
        split2(sacc[t0 + 1][0], sacc[t0 + 1][1], eh[kk][2], el[kk][2]);
        split2(sacc[t0 + 1][2], sacc[t0 + 1][3], eh[kk][3], el[kk][3]);
    }

    // ---------------- GEMM2: C[n][h] = sum_m E[n][m] * Wp[h][m] ----------------
    float* outb = out + (size_t)b * HDIM * NDIM;
    const int rr = lid >> 2, qq = lid & 3;

    for (int hc2 = 0; hc2 < 8; hc2++) {
        const int p = hc2 & 1;
        CP_WAIT(0);
        __syncthreads();                 // WB[p] visible; STG[p] free
        if (hc2 < 7) { issue_w(hc2 + 1, p ^ 1); CP_COMMIT(); }

        float cacc[8][4];
#pragma unroll
        for (int t = 0; t < 8; t++)
#pragma unroll
            for (int j = 0; j < 4; j++) cacc[t][j] = 0.f;

        const uint32_t whi = sbase + OFF_WB + p * WB_SZ;
        const uint32_t wlo = whi + 17408;
#pragma unroll
        for (int kk = 0; kk < 8; kk++) {
#pragma unroll
            for (int pr = 0; pr < 2; pr++) {         // tp pair (2pr, 2pr+1)
                uint32_t bh0[4], bl0[4], bh1[4], bl1[4];
                uint32_t bo0 = b_off_w + (uint32_t)((2 * pr) * 16 * PADW + kk * 16) * 2;
                uint32_t bo1 = b_off_w + (uint32_t)((2 * pr + 1) * 16 * PADW + kk * 16) * 2;
                ldsm4(bh0, whi + bo0);
                ldsm4(bh1, whi + bo1);
                ldsm4(bl0, wlo + bo0);
                ldsm4(bl1, wlo + bo1);
                float* A0 = cacc[4 * pr + 0];
                float* A1 = cacc[4 * pr + 1];
                float* A2 = cacc[4 * pr + 2];
                float* A3 = cacc[4 * pr + 3];
                mma16816(A0, eh[kk], bh0[0], bh0[1]);
                mma16816(A1, eh[kk], bh0[2], bh0[3]);
                mma16816(A2, eh[kk], bh1[0], bh1[1]);
                mma16816(A3, eh[kk], bh1[2], bh1[3]);
                mma16816(A0, eh[kk], bl0[0], bl0[1]);
                mma16816(A1, eh[kk], bl0[2], bl0[3]);
                mma16816(A2, eh[kk], bl1[0], bl1[1]);
                mma16816(A3, eh[kk], bl1[2], bl1[3]);
                mma16816(A0, el[kk], bh0[0], bh0[1]);
                mma16816(A1, el[kk], bh0[2], bh0[3]);
                mma16816(A2, el[kk], bh1[0], bh1[1]);
                mma16816(A3, el[kk], bh1[2], bh1[3]);
            }
        }

        // scale by 1/sum and stage transposed into STG[p]: stg[h_local][n]
        float* stg = (float*)(smem + OFF_STG + p * STG_SZ);
#pragma unroll
        for (int t = 0; t < 8; t++) {
            int hcl = t * 8 + 2 * qq;
            int n   = wid * 16 + rr;
            stg[(size_t)hcl * STGS + n]           = cacc[t][0] * r0;
            stg[(size_t)(hcl + 1) * STGS + n]     = cacc[t][1] * r0;
            stg[(size_t)hcl * STGS + n + 8]       = cacc[t][2] * r1;
            stg[(size_t)(hcl + 1) * STGS + n + 8] = cacc[t][3] * r1;
        }
        __syncthreads();                 // stage writes visible

        // coalesced fp32 store: out[b][hc2*64+hr][n0 + ...]
#pragma unroll
        for (int it = 0; it < 8; it++) {
            int f = it * 128 + tid, hr = f >> 4, n4 = (f & 15) << 2;
            float4 v = *(const float4*)(stg + (size_t)hr * STGS + n4);
            *(float4*)(outb + (size_t)(hc2 * 64 + hr) * NDIM + n0 + n4) = v;
        }
        // no end barrier: STG[p] reused only in hc2+2, after the next top-sync
    }
}

// ============================================================
extern "C" void kernel_launch(void* const* d_in, const int* in_sizes, int n_in,
                              void* d_out, int out_size) {
    const float* H      = (const float*)d_in[0];  // [32,512,64,64]
    const float* W      = (const float*)d_in[1];  // [32,256,128]
    const float* head_w = (const float*)d_in[2];  // [512,256]
    float* out = (float*)d_out;

    cudaFuncSetAttribute(attn_kernel,
                         cudaFuncAttributeMaxDynamicSharedMemorySize, SMEM_DYN);

    proj_kernel<<<dim3(4, B_DIM), 256>>>(W, head_w);
    attn_kernel<<<dim3(NDIM / 64, B_DIM), 128, SMEM_DYN>>>(H, out);
}

// round 10
// speedup vs baseline: 1.2333x; 1.0736x over previous
#include <cuda_runtime.h>
#include <cuda_bf16.h>
#include <cstdint>
#include <cstddef>

#define B_DIM 32
#define HDIM  512
#define NDIM  4096
#define MDIM  128
#define TDIM  256

// __device__ scratch (allocation-free rule). Wp as bf16 hi/lo, two layouts.
__device__ __align__(16) __nv_bfloat16 g_WpT_hi[B_DIM * MDIM * HDIM]; // [b][m][h]
__device__ __align__(16) __nv_bfloat16 g_WpT_lo[B_DIM * MDIM * HDIM];
__device__ __align__(16) __nv_bfloat16 g_Wp_hi [B_DIM * HDIM * MDIM]; // [b][h][m]
__device__ __align__(16) __nv_bfloat16 g_Wp_lo [B_DIM * HDIM * MDIM];

// ---------------- helpers (all non-arch-specific PTX) ----------------
__device__ __forceinline__ uint32_t smem_u32(const void* p) {
    uint32_t a;
    asm("{ .reg .u64 t; cvta.to.shared.u64 t, %1; cvt.u32.u64 %0, t; }"
        : "=r"(a) : "l"(p));
    return a;
}
__device__ __forceinline__ void ldsm4(uint32_t* r, uint32_t a) {
    asm volatile("ldmatrix.sync.aligned.m8n8.x4.shared.b16 {%0,%1,%2,%3}, [%4];"
        : "=r"(r[0]), "=r"(r[1]), "=r"(r[2]), "=r"(r[3]) : "r"(a));
}
__device__ __forceinline__ void ldsm4t(uint32_t* r, uint32_t a) {
    asm volatile("ldmatrix.sync.aligned.m8n8.x4.trans.shared.b16 {%0,%1,%2,%3}, [%4];"
        : "=r"(r[0]), "=r"(r[1]), "=r"(r[2]), "=r"(r[3]) : "r"(a));
}
__device__ __forceinline__ void mma16816(float* d, const uint32_t* a,
                                         uint32_t b0, uint32_t b1) {
    asm volatile(
        "mma.sync.aligned.m16n8k16.row.col.f32.bf16.bf16.f32 "
        "{%0,%1,%2,%3}, {%4,%5,%6,%7}, {%8,%9}, {%0,%1,%2,%3};"
        : "+f"(d[0]), "+f"(d[1]), "+f"(d[2]), "+f"(d[3])
        : "r"(a[0]), "r"(a[1]), "r"(a[2]), "r"(a[3]), "r"(b0), "r"(b1));
}
__device__ __forceinline__ void split2(float x, float y, uint32_t& hi, uint32_t& lo) {
    __nv_bfloat16 xh = __float2bfloat16(x);
    __nv_bfloat16 yh = __float2bfloat16(y);
    __nv_bfloat16 xl = __float2bfloat16(x - __bfloat162float(xh));
    __nv_bfloat16 yl = __float2bfloat16(y - __bfloat162float(yh));
    hi = (uint32_t)__bfloat16_as_ushort(xh) | ((uint32_t)__bfloat16_as_ushort(yh) << 16);
    lo = (uint32_t)__bfloat16_as_ushort(xl) | ((uint32_t)__bfloat16_as_ushort(yl) << 16);
}
#define CP_ASYNC16(dst, src)                                                   \
    asm volatile("cp.async.cg.shared.global [%0], [%1], 16;"                   \
                 :: "r"(dst), "l"(src))
#define CP_COMMIT() asm volatile("cp.async.commit_group;" ::: "memory")
#define CP_WAIT(n)  asm volatile("cp.async.wait_group %0;" :: "n"(n) : "memory")

// ============================================================
// Kernel 1: Wp = head_w x W (fp32 scalar, 8x8 tiles), with the
// next tile's LDGs prefetched into registers during the FMA loop.
// Grid (4, 32), 256 threads. Bit-identical math to R7.
// ============================================================
__global__ __launch_bounds__(256) void proj_kernel(const float* __restrict__ W,
                                                   const float* __restrict__ head_w) {
    __shared__ float sA[32][128];  // sA[t][h]
    __shared__ float sB[32][128];  // sB[t][m]
    const int tid = threadIdx.x;
    const int b   = blockIdx.y;
    const int h0  = blockIdx.x * 128;
    const int tx  = tid & 15, ty = tid >> 4;
    const int ra_r = tid >> 1, ra_half = tid & 1;
    const int rb_r = tid >> 3, rb_part = tid & 7;

    float acc[8][8];
#pragma unroll
    for (int i = 0; i < 8; i++)
#pragma unroll
        for (int j = 0; j < 8; j++) acc[i][j] = 0.f;

    const float* Wb = W + (size_t)b * TDIM * MDIM;

    float4 ra[4], rb[4];
    auto ldg_tiles = [&](int t0) {
        const float4* srcA =
            (const float4*)(head_w + (size_t)(h0 + ra_r) * TDIM + t0 + ra_half * 16);
        const float4* srcB =
            (const float4*)(Wb + (size_t)(t0 + rb_r) * MDIM + rb_part * 16);
#pragma unroll
        for (int i = 0; i < 4; i++) { ra[i] = srcA[i]; rb[i] = srcB[i]; }
    };

    ldg_tiles(0);
    for (int t0 = 0; t0 < TDIM; t0 += 32) {
        // store current regs -> smem (sA transposed)
#pragma unroll
        for (int i = 0; i < 4; i++) {
            float4 v = ra[i];
            int tt = ra_half * 16 + i * 4;
            sA[tt + 0][ra_r] = v.x; sA[tt + 1][ra_r] = v.y;
            sA[tt + 2][ra_r] = v.z; sA[tt + 3][ra_r] = v.w;
        }
        {
            float4* dst = (float4*)(&sB[rb_r][rb_part * 16]);
#pragma unroll
            for (int i = 0; i < 4; i++) dst[i] = rb[i];
        }
        __syncthreads();
        if (t0 + 32 < TDIM) ldg_tiles(t0 + 32);   // overlaps FMA below

#pragma unroll
        for (int t = 0; t < 32; t++) {
            float a[8], bb[8];
#pragma unroll
            for (int i = 0; i < 8; i++) a[i] = sA[t][ty * 8 + i];
#pragma unroll
            for (int j = 0; j < 8; j++) bb[j] = sB[t][tx * 8 + j];
#pragma unroll
            for (int i = 0; i < 8; i++)
#pragma unroll
                for (int j = 0; j < 8; j++) acc[i][j] = fmaf(a[i], bb[j], acc[i][j]);
        }
        __syncthreads();
    }
#pragma unroll
    for (int i = 0; i < 8; i++) {
        int h = h0 + ty * 8 + i;
#pragma unroll
        for (int j = 0; j < 8; j++) {
            int m = tx * 8 + j;
            float v = acc[i][j];
            __nv_bfloat16 hi = __float2bfloat16(v);
            __nv_bfloat16 lo = __float2bfloat16(v - __bfloat162float(hi));
            size_t pidx = ((size_t)b * HDIM + h) * MDIM + m;
            g_Wp_hi[pidx] = hi;  g_Wp_lo[pidx] = lo;
            size_t tidx = ((size_t)b * MDIM + m) * HDIM + h;
            g_WpT_hi[tidx] = hi; g_WpT_lo[tidx] = lo;
        }
    }
}

// ============================================================
// Kernel 2: fused scores -> softmax -> output.
// CTA = (batch b, 64-row n-tile), 128 threads = 4 warps x 16 n-rows.
// 3 CTAs per SM (smem 59392 B, regs capped by launch_bounds(128,3)):
// smaller k/h chunks (32) so three independent CTAs fill the tensor
// pipe across each other's convert/softmax/barrier phases.
//
// SMEM union (bytes):
//   GEMM1: KB0 @0 (20480 = hi 10240 + lo 10240), KB1 @20480 (end 40960),
//          Q0 @40960 (hi 4608 + lo 4608), Q1 @50176     -> end 59392
//   GEMM2: WB0 @0 (17408 = hi 8704 + lo 8704), WB1 @17408 (end 34816),
//          STG0 @34816 (8704), STG1 @43520              -> end 52224
// ============================================================
#define PADQ 72      // Q tile [k=32][n=64] bf16 row stride (144 B rows)
#define PADK 40      // K tile [m=128][k=32] bf16 row stride (80 B rows)
#define PADW 136     // W tile [h=32][m=128] bf16 row stride (272 B rows)
#define STGS 68      // out stage [h=32][n=64] fp32 row stride
#define OFF_KB  0
#define KB_SZ   20480
#define OFF_Q   40960
#define Q_SZ    9216
#define OFF_WB  0
#define WB_SZ   17408
#define OFF_STG 34816
#define STG_SZ  8704
#define SMEM_DYN 59392

__global__ __launch_bounds__(128, 3)
void attn_kernel(const float* __restrict__ H, float* __restrict__ out) {
    extern __shared__ char smem[];
    const uint32_t sbase = smem_u32(smem);

    const int tid = threadIdx.x;
    const int wid = tid >> 5;
    const int lid = tid & 31;
    const int b   = blockIdx.y;
    const int n0  = blockIdx.x * 64;

    const float* Hb = H + (size_t)b * HDIM * NDIM + n0;
    const __nv_bfloat16* KTh = g_WpT_hi + (size_t)b * MDIM * HDIM;
    const __nv_bfloat16* KTl = g_WpT_lo + (size_t)b * MDIM * HDIM;
    const __nv_bfloat16* Wph = g_Wp_hi  + (size_t)b * HDIM * MDIM;
    const __nv_bfloat16* Wpl = g_Wp_lo  + (size_t)b * HDIM * MDIM;

    // per-lane ldmatrix geometry (same fragment mapping as passing R7/R9)
    const int g  = lid >> 3, lr = lid & 7;
    const int arow = ((g & 2) ? 8 : 0) + lr;                 // + kk*16
    const int acol = wid * 16 + ((g & 1) ? 8 : 0);           // n (0..63)
    const uint32_t a_off = (uint32_t)(arow * PADQ + acol) * 2;
    const int brow = ((g >> 1) ? 8 : 0) + lr;                // + tp*16
    const int bcol = (g & 1) ? 8 : 0;                        // + kk*16
    const uint32_t b_off_k = (uint32_t)(brow * PADK + bcol) * 2;
    const uint32_t b_off_w = (uint32_t)(brow * PADW + bcol) * 2;

    // ---- async issue helpers ----
    auto issue_k = [&](int hc, int p) {
        uint32_t dh = sbase + OFF_KB + p * KB_SZ;
        uint32_t dl = dh + 10240;
        int k0 = hc * 32;
#pragma unroll
        for (int it = 0; it < 4; it++) {
            int f = it * 128 + tid, m = f >> 2, c8 = (f & 3) << 3;
            uint32_t o = (uint32_t)(m * PADK + c8) * 2;
            CP_ASYNC16(dh + o, KTh + (size_t)m * HDIM + k0 + c8);
            CP_ASYNC16(dl + o, KTl + (size_t)m * HDIM + k0 + c8);
        }
    };
    auto issue_w = [&](int hc2, int p) {
        uint32_t dh = sbase + OFF_WB + p * WB_SZ;
        uint32_t dl = dh + 8704;
#pragma unroll
        for (int it = 0; it < 4; it++) {
            int f = it * 128 + tid, hr = f >> 4, c8 = (f & 15) << 3;
            uint32_t o = (uint32_t)(hr * PADW + c8) * 2;
            CP_ASYNC16(dh + o, Wph + (size_t)(hc2 * 32 + hr) * MDIM + c8);
            CP_ASYNC16(dl + o, Wpl + (size_t)(hc2 * 32 + hr) * MDIM + c8);
        }
    };
    // Q chunk [k=32][n=64] -> registers (4 float4/thread)
    auto ldg_q = [&](int hc, float4* qv) {
#pragma unroll
        for (int it = 0; it < 4; it++) {
            int f = it * 128 + tid, hr = f >> 4, c4 = (f & 15) << 2;
            qv[it] = *(const float4*)(Hb + (size_t)(hc * 32 + hr) * NDIM + c4);
        }
    };
    auto conv_q = [&](const float4* qv, int q) {
        uint32_t base_h = OFF_Q + q * Q_SZ;
#pragma unroll
        for (int it = 0; it < 4; it++) {
            int f = it * 128 + tid, hr = f >> 4, c4 = (f & 15) << 2;
            uint32_t h01, l01, h23, l23;
            split2(qv[it].x, qv[it].y, h01, l01);
            split2(qv[it].z, qv[it].w, h23, l23);
            uint32_t off = (uint32_t)(hr * PADQ + c4) * 2;
            *(uint2*)(smem + base_h + off)        = make_uint2(h01, h23);
            *(uint2*)(smem + base_h + 4608 + off) = make_uint2(l01, l23);
        }
    };

    // ---------------- GEMM1: S[n][m] = sum_h Q[n][h] * WpT[m][h] ----------------
    float sacc[16][4];
#pragma unroll
    for (int t = 0; t < 16; t++)
#pragma unroll
        for (int j = 0; j < 4; j++) sacc[t][j] = 0.f;

    float4 qv[4];
    issue_k(0, 0); CP_COMMIT();
    ldg_q(0, qv);
    conv_q(qv, 0);
    ldg_q(1, qv);

    for (int hc = 0; hc < 16; hc++) {
        const int p = hc & 1;
        CP_WAIT(0);
        __syncthreads();                 // K[p] + Q[p] visible to all warps
        if (hc < 15) {
            issue_k(hc + 1, p ^ 1); CP_COMMIT();
            conv_q(qv, p ^ 1);
        }
        if (hc < 14) ldg_q(hc + 2, qv);

        const uint32_t qhi = sbase + OFF_Q + p * Q_SZ;
        const uint32_t qlo = qhi + 4608;
        const uint32_t khi = sbase + OFF_KB + p * KB_SZ;
        const uint32_t klo = khi + 10240;
#pragma unroll
        for (int kk = 0; kk < 2; kk++) {
            uint32_t ah[4], al[4];
            uint32_t aoff = a_off + (uint32_t)(kk * 16 * PADQ) * 2;
            ldsm4t(ah, qhi + aoff);
            ldsm4t(al, qlo + aoff);
#pragma unroll
            for (int pr = 0; pr < 4; pr++) {         // tp pair (2pr, 2pr+1)
                uint32_t bh0[4], bl0[4], bh1[4], bl1[4];
                uint32_t bo0 = b_off_k + (uint32_t)((2 * pr) * 16 * PADK + kk * 16) * 2;
                uint32_t bo1 = b_off_k + (uint32_t)((2 * pr + 1) * 16 * PADK + kk * 16) * 2;
                ldsm4(bh0, khi + bo0);
                ldsm4(bh1, khi + bo1);
                ldsm4(bl0, klo + bo0);
                ldsm4(bl1, klo + bo1);
                float* A0 = sacc[4 * pr + 0];
                float* A1 = sacc[4 * pr + 1];
                float* A2 = sacc[4 * pr + 2];
                float* A3 = sacc[4 * pr + 3];
                mma16816(A0, ah, bh0[0], bh0[1]);
                mma16816(A1, ah, bh0[2], bh0[3]);
                mma16816(A2, ah, bh1[0], bh1[1]);
                mma16816(A3, ah, bh1[2], bh1[3]);
                mma16816(A0, ah, bl0[0], bl0[1]);
                mma16816(A1, ah, bl0[2], bl0[3]);
                mma16816(A2, ah, bl1[0], bl1[1]);
                mma16816(A3, ah, bl1[2], bl1[3]);
                mma16816(A0, al, bh0[0], bh0[1]);
                mma16816(A1, al, bh0[2], bh0[3]);
                mma16816(A2, al, bh1[0], bh1[1]);
                mma16816(A3, al, bh1[2], bh1[3]);
            }
        }
    }

    // prefetch GEMM2 chunk 0 (WB0 @0..17408 aliases only dead KB0)
    issue_w(0, 0); CP_COMMIT();

    // ---------------- softmax over m (registers only) ----------------
    float mx0 = -3.4e38f, mx1 = -3.4e38f;
#pragma unroll
    for (int t = 0; t < 16; t++) {
        mx0 = fmaxf(mx0, fmaxf(sacc[t][0], sacc[t][1]));
        mx1 = fmaxf(mx1, fmaxf(sacc[t][2], sacc[t][3]));
    }
    mx0 = fmaxf(mx0, __shfl_xor_sync(0xFFFFFFFFu, mx0, 1));
    mx0 = fmaxf(mx0, __shfl_xor_sync(0xFFFFFFFFu, mx0, 2));
    mx1 = fmaxf(mx1, __shfl_xor_sync(0xFFFFFFFFu, mx1, 1));
    mx1 = fmaxf(mx1, __shfl_xor_sync(0xFFFFFFFFu, mx1, 2));
    float s0 = 0.f, s1 = 0.f;
#pragma unroll
    for (int t = 0; t < 16; t++) {
        sacc[t][0] = __expf(sacc[t][0] - mx0);
        sacc[t][1] = __expf(sacc[t][1] - mx0);
        sacc[t][2] = __expf(sacc[t][2] - mx1);
        sacc[t][3] = __expf(sacc[t][3] - mx1);
        s0 += sacc[t][0] + sacc[t][1];
        s1 += sacc[t][2] + sacc[t][3];
    }
    s0 += __shfl_xor_sync(0xFFFFFFFFu, s0, 1);
    s0 += __shfl_xor_sync(0xFFFFFFFFu, s0, 2);
    s1 += __shfl_xor_sync(0xFFFFFFFFu, s1, 1);
    s1 += __shfl_xor_sync(0xFFFFFFFFu, s1, 2);
    const float r0 = 1.0f / s0, r1 = 1.0f / s1;

    // Repack unnormalized E into GEMM2 A-fragments (k = m), hi/lo split.
    uint32_t eh[8][4], el[8][4];
#pragma unroll
    for (int kk = 0; kk < 8; kk++) {
        int t0 = kk * 2;
        split2(sacc[t0][0],     sacc[t0][1],     eh[kk][0], el[kk][0]);
        split2(sacc[t0][2],     sacc[t0][3],     eh[kk][1], el[kk][1]);
        split2(sacc[t0 + 1][0], sacc[t0 + 1][1], eh[kk][2], el[kk][2]);
        split2(sacc[t0 + 1][2], sacc[t0 + 1][3], eh[kk][3], el[kk][3]);
    }

    // ---------------- GEMM2: C[n][h] = sum_m E[n][m] * Wp[h][m] ----------------
    float* outb = out + (size_t)b * HDIM * NDIM;
    const int rr = lid >> 2, qq = lid & 3;

    for (int hc2 = 0; hc2 < 16; hc2++) {
        const int p = hc2 & 1;
        CP_WAIT(0);
        __syncthreads();                 // WB[p] visible; STG[p] free
        if (hc2 < 15) { issue_w(hc2 + 1, p ^ 1); CP_COMMIT(); }

        float cacc[4][4];
#pragma unroll
        for (int t = 0; t < 4; t++)
#pragma unroll
            for (int j = 0; j < 4; j++) cacc[t][j] = 0.f;

        const uint32_t whi = sbase + OFF_WB + p * WB_SZ;
        const uint32_t wlo = whi + 8704;
#pragma unroll
        for (int kk = 0; kk < 8; kk++) {
            uint32_t bh0[4], bl0[4], bh1[4], bl1[4];
            uint32_t bo0 = b_off_w + (uint32_t)(kk * 16) * 2;
            uint32_t bo1 = b_off_w + (uint32_t)(16 * PADW + kk * 16) * 2;
            ldsm4(bh0, whi + bo0);
            ldsm4(bh1, whi + bo1);
            ldsm4(bl0, wlo + bo0);
            ldsm4(bl1, wlo + bo1);
            float* A0 = cacc[0];
            float* A1 = cacc[1];
            float* A2 = cacc[2];
            float* A3 = cacc[3];
            mma16816(A0, eh[kk], bh0[0], bh0[1]);
            mma16816(A1, eh[kk], bh0[2], bh0[3]);
            mma16816(A2, eh[kk], bh1[0], bh1[1]);
            mma16816(A3, eh[kk], bh1[2], bh1[3]);
            mma16816(A0, eh[kk], bl0[0], bl0[1]);
            mma16816(A1, eh[kk], bl0[2], bl0[3]);
            mma16816(A2, eh[kk], bl1[0], bl1[1]);
            mma16816(A3, eh[kk], bl1[2], bl1[3]);
            mma16816(A0, el[kk], bh0[0], bh0[1]);
            mma16816(A1, el[kk], bh0[2], bh0[3]);
            mma16816(A2, el[kk], bh1[0], bh1[1]);
            mma16816(A3, el[kk], bh1[2], bh1[3]);
        }

        // scale by 1/sum and stage transposed into STG[p]: stg[h_local][n]
        float* stg = (float*)(smem + OFF_STG + p * STG_SZ);
#pragma unroll
        for (int t = 0; t < 4; t++) {
            int hcl = t * 8 + 2 * qq;
            int n   = wid * 16 + rr;
            stg[(size_t)hcl * STGS + n]           = cacc[t][0] * r0;
            stg[(size_t)(hcl + 1) * STGS + n]     = cacc[t][1] * r0;
            stg[(size_t)hcl * STGS + n + 8]       = cacc[t][2] * r1;
            stg[(size_t)(hcl + 1) * STGS + n + 8] = cacc[t][3] * r1;
        }
        __syncthreads();                 // stage writes visible

        // coalesced fp32 store: out[b][hc2*32+hr][n0 + ...]
#pragma unroll
        for (int it = 0; it < 4; it++) {
            int f = it * 128 + tid, hr = f >> 4, n4 = (f & 15) << 2;
            float4 v = *(const float4*)(stg + (size_t)hr * STGS + n4);
            *(float4*)(outb + (size_t)(hc2 * 32 + hr) * NDIM + n0 + n4) = v;
        }
        // no end barrier: STG[p] reused only in hc2+2, after the next top-sync
    }
}

// ============================================================
extern "C" void kernel_launch(void* const* d_in, const int* in_sizes, int n_in,
                              void* d_out, int out_size) {
    const float* H      = (const float*)d_in[0];  // [32,512,64,64]
    const float* W      = (const float*)d_in[1];  // [32,256,128]
    const float* head_w = (const float*)d_in[2];  // [512,256]
    float* out = (float*)d_out;

    cudaFuncSetAttribute(attn_kernel,
                         cudaFuncAttributeMaxDynamicSharedMemorySize, SMEM_DYN);

    proj_kernel<<<dim3(4, B_DIM), 256>>>(W, head_w);
    attn_kernel<<<dim3(NDIM / 64, B_DIM), 128, SMEM_DYN>>>(H, out);
}

// round 11
// speedup vs baseline: 1.3678x; 1.1091x over previous
#include <cuda_runtime.h>
#include <cuda_bf16.h>
#include <cstdint>
#include <cstddef>

#define B_DIM 32
#define HDIM  512
#define NDIM  4096
#define MDIM  128
#define TDIM  256

// __device__ scratch (allocation-free rule). Wp as bf16 hi/lo, two layouts.
__device__ __align__(16) __nv_bfloat16 g_WpT_hi[B_DIM * MDIM * HDIM]; // [b][m][h]
__device__ __align__(16) __nv_bfloat16 g_WpT_lo[B_DIM * MDIM * HDIM];
__device__ __align__(16) __nv_bfloat16 g_Wp_hi [B_DIM * HDIM * MDIM]; // [b][h][m]
__device__ __align__(16) __nv_bfloat16 g_Wp_lo [B_DIM * HDIM * MDIM];

// ---------------- helpers (all non-arch-specific PTX) ----------------
__device__ __forceinline__ uint32_t smem_u32(const void* p) {
    uint32_t a;
    asm("{ .reg .u64 t; cvta.to.shared.u64 t, %1; cvt.u32.u64 %0, t; }"
        : "=r"(a) : "l"(p));
    return a;
}
__device__ __forceinline__ void ldsm4(uint32_t* r, uint32_t a) {
    asm volatile("ldmatrix.sync.aligned.m8n8.x4.shared.b16 {%0,%1,%2,%3}, [%4];"
        : "=r"(r[0]), "=r"(r[1]), "=r"(r[2]), "=r"(r[3]) : "r"(a));
}
__device__ __forceinline__ void ldsm4t(uint32_t* r, uint32_t a) {
    asm volatile("ldmatrix.sync.aligned.m8n8.x4.trans.shared.b16 {%0,%1,%2,%3}, [%4];"
        : "=r"(r[0]), "=r"(r[1]), "=r"(r[2]), "=r"(r[3]) : "r"(a));
}
__device__ __forceinline__ void mma16816(float* d, const uint32_t* a,
                                         uint32_t b0, uint32_t b1) {
    asm volatile(
        "mma.sync.aligned.m16n8k16.row.col.f32.bf16.bf16.f32 "
        "{%0,%1,%2,%3}, {%4,%5,%6,%7}, {%8,%9}, {%0,%1,%2,%3};"
        : "+f"(d[0]), "+f"(d[1]), "+f"(d[2]), "+f"(d[3])
        : "r"(a[0]), "r"(a[1]), "r"(a[2]), "r"(a[3]), "r"(b0), "r"(b1));
}
__device__ __forceinline__ void split2(float x, float y, uint32_t& hi, uint32_t& lo) {
    __nv_bfloat16 xh = __float2bfloat16(x);
    __nv_bfloat16 yh = __float2bfloat16(y);
    __nv_bfloat16 xl = __float2bfloat16(x - __bfloat162float(xh));
    __nv_bfloat16 yl = __float2bfloat16(y - __bfloat162float(yh));
    hi = (uint32_t)__bfloat16_as_ushort(xh) | ((uint32_t)__bfloat16_as_ushort(yh) << 16);
    lo = (uint32_t)__bfloat16_as_ushort(xl) | ((uint32_t)__bfloat16_as_ushort(yl) << 16);
}
#define CP_ASYNC16(dst, src)                                                   \
    asm volatile("cp.async.cg.shared.global [%0], [%1], 16;"                   \
                 :: "r"(dst), "l"(src))
#define CP_COMMIT() asm volatile("cp.async.commit_group;" ::: "memory")
#define CP_WAIT(n)  asm volatile("cp.async.wait_group %0;" :: "n"(n) : "memory")

// ============================================================
// Kernel 1 (NEW, HMMA): WpT[b,m,h] / Wp[b,h,m] via 3-split bf16 MMA.
//   D[m][h] = sum_t W[b][t][m] * head_w[h0+h][t]
// Structurally identical to the proven attn GEMM1:
//   A tile = W chunk, stored [k=32][m=128] (ldsm4t path)
//   B tile = head_w slice, stored [h=128][k=32] (ldsm4 path)
// Grid (4, 32): (h-slice, batch). 256 threads = 8 warps x 16 m-rows.
// ============================================================
#define PPADA 136    // A tile [k=32][m=128] bf16 row stride
#define PPADB 40     // B tile [h=128][k=32] bf16 row stride
#define PSTG  133    // fp32 stage [m=128][h=128] row stride (conflict-mitigated)
#define POFF_A  0
#define PA_HALF 8704          // 32*136*2
#define POFF_B  17408
#define PB_HALF 10240         // 128*40*2
#define PSMEM   69632         // stage 128*133*4 = 68096 (aliases tiles after sync)

__global__ __launch_bounds__(256) void proj_kernel(const float* __restrict__ W,
                                                   const float* __restrict__ head_w) {
    extern __shared__ char smem[];
    const uint32_t sbase = smem_u32(smem);

    const int tid = threadIdx.x;
    const int wid = tid >> 5;
    const int lid = tid & 31;
    const int b   = blockIdx.y;
    const int h0  = blockIdx.x * 128;

    const float* Wb = W + (size_t)b * TDIM * MDIM;

    // lane geometry — copied verbatim from attn GEMM1
    const int g  = lid >> 3, lr = lid & 7;
    const int arow = ((g & 2) ? 8 : 0) + lr;                 // + kk*16
    const int acol = wid * 16 + ((g & 1) ? 8 : 0);           // m (0..127)
    const uint32_t a_off = (uint32_t)(arow * PPADA + acol) * 2;
    const int brow = ((g >> 1) ? 8 : 0) + lr;                // + tp*16
    const int bcol = (g & 1) ? 8 : 0;                        // + kk*16
    const uint32_t b_off = (uint32_t)(brow * PPADB + bcol) * 2;

    // ldg chunk kc into regs: A = W rows t, B = head_w rows h
    float4 ra[4], rb[4];
    auto ldg_chunk = [&](int kc) {
#pragma unroll
        for (int it = 0; it < 4; it++) {
            int fa = it * 256 + tid;                   // 0..1023
            int ar = fa >> 5, ac4 = (fa & 31) << 2;    // k-row, m col
            ra[it] = *(const float4*)(Wb + (size_t)(kc * 32 + ar) * MDIM + ac4);
            int br = fa >> 3, bc4 = (fa & 7) << 2;     // h-row, k col
            rb[it] = *(const float4*)(head_w + (size_t)(h0 + br) * TDIM + kc * 32 + bc4);
        }
    };
    auto conv_chunk = [&]() {
#pragma unroll
        for (int it = 0; it < 4; it++) {
            int fa = it * 256 + tid;
            int ar = fa >> 5, ac4 = (fa & 31) << 2;
            uint32_t h01, l01, h23, l23;
            split2(ra[it].x, ra[it].y, h01, l01);
            split2(ra[it].z, ra[it].w, h23, l23);
            uint32_t off = (uint32_t)(ar * PPADA + ac4) * 2;
            *(uint2*)(smem + POFF_A + off)            = make_uint2(h01, h23);
            *(uint2*)(smem + POFF_A + PA_HALF + off)  = make_uint2(l01, l23);
            int br = fa >> 3, bc4 = (fa & 7) << 2;
            split2(rb[it].x, rb[it].y, h01, l01);
            split2(rb[it].z, rb[it].w, h23, l23);
            off = (uint32_t)(br * PPADB + bc4) * 2;
            *(uint2*)(smem + POFF_B + off)            = make_uint2(h01, h23);
            *(uint2*)(smem + POFF_B + PB_HALF + off)  = make_uint2(l01, l23);
        }
    };

    float sacc[16][4];
#pragma unroll
    for (int t = 0; t < 16; t++)
#pragma unroll
        for (int j = 0; j < 4; j++) sacc[t][j] = 0.f;

    ldg_chunk(0);
    for (int kc = 0; kc < 8; kc++) {
        conv_chunk();
        __syncthreads();                 // tiles visible
        if (kc < 7) ldg_chunk(kc + 1);   // overlaps MMA

        const uint32_t ahi = sbase + POFF_A, alo = ahi + PA_HALF;
        const uint32_t bhi = sbase + POFF_B, blo = bhi + PB_HALF;
#pragma unroll
        for (int kk = 0; kk < 2; kk++) {
            uint32_t ah[4], al[4];
            uint32_t aoff = a_off + (uint32_t)(kk * 16 * PPADA) * 2;
            ldsm4t(ah, ahi + aoff);
            ldsm4t(al, alo + aoff);
#pragma unroll
            for (int pr = 0; pr < 4; pr++) {
                uint32_t bh0[4], bl0[4], bh1[4], bl1[4];
                uint32_t bo0 = b_off + (uint32_t)((2 * pr) * 16 * PPADB + kk * 16) * 2;
                uint32_t bo1 = b_off + (uint32_t)((2 * pr + 1) * 16 * PPADB + kk * 16) * 2;
                ldsm4(bh0, bhi + bo0);
                ldsm4(bh1, bhi + bo1);
                ldsm4(bl0, blo + bo0);
                ldsm4(bl1, blo + bo1);
                float* A0 = sacc[4 * pr + 0];
                float* A1 = sacc[4 * pr + 1];
                float* A2 = sacc[4 * pr + 2];
                float* A3 = sacc[4 * pr + 3];
                mma16816(A0, ah, bh0[0], bh0[1]);
                mma16816(A1, ah, bh0[2], bh0[3]);
                mma16816(A2, ah, bh1[0], bh1[1]);
                mma16816(A3, ah, bh1[2], bh1[3]);
                mma16816(A0, ah, bl0[0], bl0[1]);
                mma16816(A1, ah, bl0[2], bl0[3]);
                mma16816(A2, ah, bl1[0], bl1[1]);
                mma16816(A3, ah, bl1[2], bl1[3]);
                mma16816(A0, al, bh0[0], bh0[1]);
                mma16816(A1, al, bh0[2], bh0[3]);
                mma16816(A2, al, bh1[0], bh1[1]);
                mma16816(A3, al, bh1[2], bh1[3]);
            }
        }
        __syncthreads();                 // tile buffers free for next conv
    }

    // ---- epilogue: stage D[m][h] fp32, then split-store both layouts ----
    float* stg = (float*)smem;           // aliases tiles (all MMA reads done)
    const int rr = lid >> 2, qq = lid & 3;
#pragma unroll
    for (int t = 0; t < 16; t++) {
        int hcl = t * 8 + 2 * qq;
        int m   = wid * 16 + rr;
        stg[(size_t)m * PSTG + hcl]           = sacc[t][0];
        stg[(size_t)m * PSTG + hcl + 1]       = sacc[t][1];
        stg[(size_t)(m + 8) * PSTG + hcl]     = sacc[t][2];
        stg[(size_t)(m + 8) * PSTG + hcl + 1] = sacc[t][3];
    }
    __syncthreads();

    // WpT[b][m][h0+h]: rows m, coalesced over h
#pragma unroll
    for (int it = 0; it < 16; it++) {
        int f = it * 256 + tid;          // 0..4095 groups of 4 h
        int m = f >> 5, c4 = (f & 31) << 2;
        const float* s = stg + (size_t)m * PSTG + c4;
        uint32_t h01, l01, h23, l23;
        split2(s[0], s[1], h01, l01);
        split2(s[2], s[3], h23, l23);
        size_t base = ((size_t)b * MDIM + m) * HDIM + h0 + c4;
        *(uint2*)(g_WpT_hi + base) = make_uint2(h01, h23);
        *(uint2*)(g_WpT_lo + base) = make_uint2(l01, l23);
    }
    // Wp[b][h0+h][m]: rows h, coalesced over m (transposed smem reads)
#pragma unroll
    for (int it = 0; it < 16; it++) {
        int f = it * 256 + tid;          // 0..4095 groups of 4 m
        int h = f >> 5, m4 = (f & 31) << 2;
        float x0 = stg[(size_t)(m4 + 0) * PSTG + h];
        float x1 = stg[(size_t)(m4 + 1) * PSTG + h];
        float x2 = stg[(size_t)(m4 + 2) * PSTG + h];
        float x3 = stg[(size_t)(m4 + 3) * PSTG + h];
        uint32_t h01, l01, h23, l23;
        split2(x0, x1, h01, l01);
        split2(x2, x3, h23, l23);
        size_t base = ((size_t)b * HDIM + h0 + h) * MDIM + m4;
        *(uint2*)(g_Wp_hi + base) = make_uint2(h01, h23);
        *(uint2*)(g_Wp_lo + base) = make_uint2(l01, l23);
    }
}

// ============================================================
// Kernel 2 (UNCHANGED from R10 best): fused scores -> softmax -> output.
// 3 CTAs/SM, 128 threads, k/h chunks of 32.
// ============================================================
#define PADQ 72
#define PADK 40
#define PADW 136
#define STGS 68
#define OFF_KB  0
#define KB_SZ   20480
#define OFF_Q   40960
#define Q_SZ    9216
#define OFF_WB  0
#define WB_SZ   17408
#define OFF_STG 34816
#define STG_SZ  8704
#define SMEM_DYN 59392

__global__ __launch_bounds__(128, 3)
void attn_kernel(const float* __restrict__ H, float* __restrict__ out) {
    extern __shared__ char smem[];
    const uint32_t sbase = smem_u32(smem);

    const int tid = threadIdx.x;
    const int wid = tid >> 5;
    const int lid = tid & 31;
    const int b   = blockIdx.y;
    const int n0  = blockIdx.x * 64;

    const float* Hb = H + (size_t)b * HDIM * NDIM + n0;
    const __nv_bfloat16* KTh = g_WpT_hi + (size_t)b * MDIM * HDIM;
    const __nv_bfloat16* KTl = g_WpT_lo + (size_t)b * MDIM * HDIM;
    const __nv_bfloat16* Wph = g_Wp_hi  + (size_t)b * HDIM * MDIM;
    const __nv_bfloat16* Wpl = g_Wp_lo  + (size_t)b * HDIM * MDIM;

    const int g  = lid >> 3, lr = lid & 7;
    const int arow = ((g & 2) ? 8 : 0) + lr;
    const int acol = wid * 16 + ((g & 1) ? 8 : 0);
    const uint32_t a_off = (uint32_t)(arow * PADQ + acol) * 2;
    const int brow = ((g >> 1) ? 8 : 0) + lr;
    const int bcol = (g & 1) ? 8 : 0;
    const uint32_t b_off_k = (uint32_t)(brow * PADK + bcol) * 2;
    const uint32_t b_off_w = (uint32_t)(brow * PADW + bcol) * 2;

    auto issue_k = [&](int hc, int p) {
        uint32_t dh = sbase + OFF_KB + p * KB_SZ;
        uint32_t dl = dh + 10240;
        int k0 = hc * 32;
#pragma unroll
        for (int it = 0; it < 4; it++) {
            int f = it * 128 + tid, m = f >> 2, c8 = (f & 3) << 3;
            uint32_t o = (uint32_t)(m * PADK + c8) * 2;
            CP_ASYNC16(dh + o, KTh + (size_t)m * HDIM + k0 + c8);
            CP_ASYNC16(dl + o, KTl + (size_t)m * HDIM + k0 + c8);
        }
    };
    auto issue_w = [&](int hc2, int p) {
        uint32_t dh = sbase + OFF_WB + p * WB_SZ;
        uint32_t dl = dh + 8704;
#pragma unroll
        for (int it = 0; it < 4; it++) {
            int f = it * 128 + tid, hr = f >> 4, c8 = (f & 15) << 3;
            uint32_t o = (uint32_t)(hr * PADW + c8) * 2;
            CP_ASYNC16(dh + o, Wph + (size_t)(hc2 * 32 + hr) * MDIM + c8);
            CP_ASYNC16(dl + o, Wpl + (size_t)(hc2 * 32 + hr) * MDIM + c8);
        }
    };
    auto ldg_q = [&](int hc, float4* qv) {
#pragma unroll
        for (int it = 0; it < 4; it++) {
            int f = it * 128 + tid, hr = f >> 4, c4 = (f & 15) << 2;
            qv[it] = *(const float4*)(Hb + (size_t)(hc * 32 + hr) * NDIM + c4);
        }
    };
    auto conv_q = [&](const float4* qv, int q) {
        uint32_t base_h = OFF_Q + q * Q_SZ;
#pragma unroll
        for (int it = 0; it < 4; it++) {
            int f = it * 128 + tid, hr = f >> 4, c4 = (f & 15) << 2;
            uint32_t h01, l01, h23, l23;
            split2(qv[it].x, qv[it].y, h01, l01);
            split2(qv[it].z, qv[it].w, h23, l23);
            uint32_t off = (uint32_t)(hr * PADQ + c4) * 2;
            *(uint2*)(smem + base_h + off)        = make_uint2(h01, h23);
            *(uint2*)(smem + base_h + 4608 + off) = make_uint2(l01, l23);
        }
    };

    float sacc[16][4];
#pragma unroll
    for (int t = 0; t < 16; t++)
#pragma unroll
        for (int j = 0; j < 4; j++) sacc[t][j] = 0.f;

    float4 qv[4];
    issue_k(0, 0); CP_COMMIT();
    ldg_q(0, qv);
    conv_q(qv, 0);
    ldg_q(1, qv);

    for (int hc = 0; hc < 16; hc++) {
        const int p = hc & 1;
        CP_WAIT(0);
        __syncthreads();
        if (hc < 15) {
            issue_k(hc + 1, p ^ 1); CP_COMMIT();
            conv_q(qv, p ^ 1);
        }
        if (hc < 14) ldg_q(hc + 2, qv);

        const uint32_t qhi = sbase + OFF_Q + p * Q_SZ;
        const uint32_t qlo = qhi + 4608;
        const uint32_t khi = sbase + OFF_KB + p * KB_SZ;
        const uint32_t klo = khi + 10240;
#pragma unroll
        for (int kk = 0; kk < 2; kk++) {
            uint32_t ah[4], al[4];
            uint32_t aoff = a_off + (uint32_t)(kk * 16 * PADQ) * 2;
            ldsm4t(ah, qhi + aoff);
            ldsm4t(al, qlo + aoff);
#pragma unroll
            for (int pr = 0; pr < 4; pr++) {
                uint32_t bh0[4], bl0[4], bh1[4], bl1[4];
                uint32_t bo0 = b_off_k + (uint32_t)((2 * pr) * 16 * PADK + kk * 16) * 2;
                uint32_t bo1 = b_off_k + (uint32_t)((2 * pr + 1) * 16 * PADK + kk * 16) * 2;
                ldsm4(bh0, khi + bo0);
                ldsm4(bh1, khi + bo1);
                ldsm4(bl0, klo + bo0);
                ldsm4(bl1, klo + bo1);
                float* A0 = sacc[4 * pr + 0];
                float* A1 = sacc[4 * pr + 1];
                float* A2 = sacc[4 * pr + 2];
                float* A3 = sacc[4 * pr + 3];
                mma16816(A0, ah, bh0[0], bh0[1]);
                mma16816(A1, ah, bh0[2], bh0[3]);
                mma16816(A2, ah, bh1[0], bh1[1]);
                mma16816(A3, ah, bh1[2], bh1[3]);
                mma16816(A0, ah, bl0[0], bl0[1]);
                mma16816(A1, ah, bl0[2], bl0[3]);
                mma16816(A2, ah, bl1[0], bl1[1]);
                mma16816(A3, ah, bl1[2], bl1[3]);
                mma16816(A0, al, bh0[0], bh0[1]);
                mma16816(A1, al, bh0[2], bh0[3]);
                mma16816(A2, al, bh1[0], bh1[1]);
                mma16816(A3, al, bh1[2], bh1[3]);
            }
        }
    }

    issue_w(0, 0); CP_COMMIT();

    float mx0 = -3.4e38f, mx1 = -3.4e38f;
#pragma unroll
    for (int t = 0; t < 16; t++) {
        mx0 = fmaxf(mx0, fmaxf(sacc[t][0], sacc[t][1]));
        mx1 = fmaxf(mx1, fmaxf(sacc[t][2], sacc[t][3]));
    }
    mx0 = fmaxf(mx0, __shfl_xor_sync(0xFFFFFFFFu, mx0, 1));
    mx0 = fmaxf(mx0, __shfl_xor_sync(0xFFFFFFFFu, mx0, 2));
    mx1 = fmaxf(mx1, __shfl_xor_sync(0xFFFFFFFFu, mx1, 1));
    mx1 = fmaxf(mx1, __shfl_xor_sync(0xFFFFFFFFu, mx1, 2));
    float s0 = 0.f, s1 = 0.f;
#pragma unroll
    for (int t = 0; t < 16; t++) {
        sacc[t][0] = __expf(sacc[t][0] - mx0);
        sacc[t][1] = __expf(sacc[t][1] - mx0);
        sacc[t][2] = __expf(sacc[t][2] - mx1);
        sacc[t][3] = __expf(sacc[t][3] - mx1);
        s0 += sacc[t][0] + sacc[t][1];
        s1 += sacc[t][2] + sacc[t][3];
    }
    s0 += __shfl_xor_sync(0xFFFFFFFFu, s0, 1);
    s0 += __shfl_xor_sync(0xFFFFFFFFu, s0, 2);
    s1 += __shfl_xor_sync(0xFFFFFFFFu, s1, 1);
    s1 += __shfl_xor_sync(0xFFFFFFFFu, s1, 2);
    const float r0 = 1.0f / s0, r1 = 1.0f / s1;

    uint32_t eh[8][4], el[8][4];
#pragma unroll
    for (int kk = 0; kk < 8; kk++) {
        int t0 = kk * 2;
        split2(sacc[t0][0],     sacc[t0][1],     eh[kk][0], el[kk][0]);
        split2(sacc[t0][2],     sacc[t0][3],     eh[kk][1], el[kk][1]);
        split2(sacc[t0 + 1][0], sacc[t0 + 1][1], eh[kk][2], el[kk][2]);
        split2(sacc[t0 + 1][2], sacc[t0 + 1][3], eh[kk][3], el[kk][3]);
    }

    float* outb = out + (size_t)b * HDIM * NDIM;
    const int rr = lid >> 2, qq = lid & 3;

    for (int hc2 = 0; hc2 < 16; hc2++) {
        const int p = hc2 & 1;
        CP_WAIT(0);
        __syncthreads();
        if (hc2 < 15) { issue_w(hc2 + 1, p ^ 1); CP_COMMIT(); }

        float cacc[4][4];
#pragma unroll
        for (int t = 0; t < 4; t++)
#pragma unroll
            for (int j = 0; j < 4; j++) cacc[t][j] = 0.f;

        const uint32_t whi = sbase + OFF_WB + p * WB_SZ;
        const uint32_t wlo = whi + 8704;
#pragma unroll
        for (int kk = 0; kk < 8; kk++) {
            uint32_t bh0[4], bl0[4], bh1[4], bl1[4];
            uint32_t bo0 = b_off_w + (uint32_t)(kk * 16) * 2;
            uint32_t bo1 = b_off_w + (uint32_t)(16 * PADW + kk * 16) * 2;
            ldsm4(bh0, whi + bo0);
            ldsm4(bh1, whi + bo1);
            ldsm4(bl0, wlo + bo0);
            ldsm4(bl1, wlo + bo1);
            float* A0 = cacc[0];
            float* A1 = cacc[1];
            float* A2 = cacc[2];
            float* A3 = cacc[3];
            mma16816(A0, eh[kk], bh0[0], bh0[1]);
            mma16816(A1, eh[kk], bh0[2], bh0[3]);
            mma16816(A2, eh[kk], bh1[0], bh1[1]);
            mma16816(A3, eh[kk], bh1[2], bh1[3]);
            mma16816(A0, eh[kk], bl0[0], bl0[1]);
            mma16816(A1, eh[kk], bl0[2], bl0[3]);
            mma16816(A2, eh[kk], bl1[0], bl1[1]);
            mma16816(A3, eh[kk], bl1[2], bl1[3]);
            mma16816(A0, el[kk], bh0[0], bh0[1]);
            mma16816(A1, el[kk], bh0[2], bh0[3]);
            mma16816(A2, el[kk], bh1[0], bh1[1]);
            mma16816(A3, el[kk], bh1[2], bh1[3]);
        }

        float* stg = (float*)(smem + OFF_STG + p * STG_SZ);
#pragma unroll
        for (int t = 0; t < 4; t++) {
            int hcl = t * 8 + 2 * qq;
            int n   = wid * 16 + rr;
            stg[(size_t)hcl * STGS + n]           = cacc[t][0] * r0;
            stg[(size_t)(hcl + 1) * STGS + n]     = cacc[t][1] * r0;
            stg[(size_t)hcl * STGS + n + 8]       = cacc[t][2] * r1;
            stg[(size_t)(hcl + 1) * STGS + n + 8] = cacc[t][3] * r1;
        }
        __syncthreads();

#pragma unroll
        for (int it = 0; it < 4; it++) {
            int f = it * 128 + tid, hr = f >> 4, n4 = (f & 15) << 2;
            float4 v = *(const float4*)(stg + (size_t)hr * STGS + n4);
            *(float4*)(outb + (size_t)(hc2 * 32 + hr) * NDIM + n0 + n4) = v;
        }
    }
}

// ============================================================
extern "C" void kernel_launch(void* const* d_in, const int* in_sizes, int n_in,
                              void* d_out, int out_size) {
    const float* H      = (const float*)d_in[0];  // [32,512,64,64]
    const float* W      = (const float*)d_in[1];  // [32,256,128]
    const float* head_w = (const float*)d_in[2];  // [512,256]
    float* out = (float*)d_out;

    cudaFuncSetAttribute(proj_kernel,
                         cudaFuncAttributeMaxDynamicSharedMemorySize, PSMEM);
    cudaFuncSetAttribute(attn_kernel,
                         cudaFuncAttributeMaxDynamicSharedMemorySize, SMEM_DYN);

    proj_kernel<<<dim3(4, B_DIM), 256, PSMEM>>>(W, head_w);
    attn_kernel<<<dim3(NDIM / 64, B_DIM), 128, SMEM_DYN>>>(H, out);
}

// round 12
// speedup vs baseline: 1.6776x; 1.2265x over previous
#include <cuda_runtime.h>
#include <cuda_bf16.h>
#include <cuda_fp16.h>
#include <cstdint>
#include <cstddef>

#define B_DIM 32
#define HDIM  512
#define NDIM  4096
#define MDIM  128
#define TDIM  256

// __device__ scratch. WpT bf16 hi/lo (GEMM1, 3-split); Wp single fp16 (GEMM2).
__device__ __align__(16) __nv_bfloat16 g_WpT_hi[B_DIM * MDIM * HDIM]; // [b][m][h]
__device__ __align__(16) __nv_bfloat16 g_WpT_lo[B_DIM * MDIM * HDIM];
__device__ __align__(16) __half        g_Wp_f16[B_DIM * HDIM * MDIM]; // [b][h][m]

// ---------------- helpers (all non-arch-specific PTX) ----------------
__device__ __forceinline__ uint32_t smem_u32(const void* p) {
    uint32_t a;
    asm("{ .reg .u64 t; cvta.to.shared.u64 t, %1; cvt.u32.u64 %0, t; }"
        : "=r"(a) : "l"(p));
    return a;
}
__device__ __forceinline__ void ldsm4(uint32_t* r, uint32_t a) {
    asm volatile("ldmatrix.sync.aligned.m8n8.x4.shared.b16 {%0,%1,%2,%3}, [%4];"
        : "=r"(r[0]), "=r"(r[1]), "=r"(r[2]), "=r"(r[3]) : "r"(a));
}
__device__ __forceinline__ void ldsm4t(uint32_t* r, uint32_t a) {
    asm volatile("ldmatrix.sync.aligned.m8n8.x4.trans.shared.b16 {%0,%1,%2,%3}, [%4];"
        : "=r"(r[0]), "=r"(r[1]), "=r"(r[2]), "=r"(r[3]) : "r"(a));
}
__device__ __forceinline__ void mma16816(float* d, const uint32_t* a,
                                         uint32_t b0, uint32_t b1) {
    asm volatile(
        "mma.sync.aligned.m16n8k16.row.col.f32.bf16.bf16.f32 "
        "{%0,%1,%2,%3}, {%4,%5,%6,%7}, {%8,%9}, {%0,%1,%2,%3};"
        : "+f"(d[0]), "+f"(d[1]), "+f"(d[2]), "+f"(d[3])
        : "r"(a[0]), "r"(a[1]), "r"(a[2]), "r"(a[3]), "r"(b0), "r"(b1));
}
__device__ __forceinline__ void mma16816f(float* d, const uint32_t* a,
                                          uint32_t b0, uint32_t b1) {
    asm volatile(
        "mma.sync.aligned.m16n8k16.row.col.f32.f16.f16.f32 "
        "{%0,%1,%2,%3}, {%4,%5,%6,%7}, {%8,%9}, {%0,%1,%2,%3};"
        : "+f"(d[0]), "+f"(d[1]), "+f"(d[2]), "+f"(d[3])
        : "r"(a[0]), "r"(a[1]), "r"(a[2]), "r"(a[3]), "r"(b0), "r"(b1));
}
__device__ __forceinline__ void split2(float x, float y, uint32_t& hi, uint32_t& lo) {
    __nv_bfloat16 xh = __float2bfloat16(x);
    __nv_bfloat16 yh = __float2bfloat16(y);
    __nv_bfloat16 xl = __float2bfloat16(x - __bfloat162float(xh));
    __nv_bfloat16 yl = __float2bfloat16(y - __bfloat162float(yh));
    hi = (uint32_t)__bfloat16_as_ushort(xh) | ((uint32_t)__bfloat16_as_ushort(yh) << 16);
    lo = (uint32_t)__bfloat16_as_ushort(xl) | ((uint32_t)__bfloat16_as_ushort(yl) << 16);
}
__device__ __forceinline__ uint32_t packh2(float x, float y) {
    __half2 h = __floats2half2_rn(x, y);
    return *(uint32_t*)&h;
}
#define CP_ASYNC16(dst, src)                                                   \
    asm volatile("cp.async.cg.shared.global [%0], [%1], 16;"                   \
                 :: "r"(dst), "l"(src))
#define CP_COMMIT() asm volatile("cp.async.commit_group;" ::: "memory")
#define CP_WAIT(n)  asm volatile("cp.async.wait_group %0;" :: "n"(n) : "memory")

// ============================================================
// Kernel 1 (HMMA, as R11): WpT bf16 hi/lo + Wp fp16 via 3-split MMA.
//   D[m][h] = sum_t W[b][t][m] * head_w[h0+h][t]
// Grid (4, 32), 256 threads = 8 warps x 16 m-rows.
// ============================================================
#define PPADA 136
#define PPADB 40
#define PSTG  133
#define POFF_A  0
#define PA_HALF 8704
#define POFF_B  17408
#define PB_HALF 10240
#define PSMEM   69632

__global__ __launch_bounds__(256) void proj_kernel(const float* __restrict__ W,
                                                   const float* __restrict__ head_w) {
    extern __shared__ char smem[];
    const uint32_t sbase = smem_u32(smem);

    const int tid = threadIdx.x;
    const int wid = tid >> 5;
    const int lid = tid & 31;
    const int b   = blockIdx.y;
    const int h0  = blockIdx.x * 128;

    const float* Wb = W + (size_t)b * TDIM * MDIM;

    const int g  = lid >> 3, lr = lid & 7;
    const int arow = ((g & 2) ? 8 : 0) + lr;
    const int acol = wid * 16 + ((g & 1) ? 8 : 0);
    const uint32_t a_off = (uint32_t)(arow * PPADA + acol) * 2;
    const int brow = ((g >> 1) ? 8 : 0) + lr;
    const int bcol = (g & 1) ? 8 : 0;
    const uint32_t b_off = (uint32_t)(brow * PPADB + bcol) * 2;

    float4 ra[4], rb[4];
    auto ldg_chunk = [&](int kc) {
#pragma unroll
        for (int it = 0; it < 4; it++) {
            int fa = it * 256 + tid;
            int ar = fa >> 5, ac4 = (fa & 31) << 2;
            ra[it] = *(const float4*)(Wb + (size_t)(kc * 32 + ar) * MDIM + ac4);
            int br = fa >> 3, bc4 = (fa & 7) << 2;
            rb[it] = *(const float4*)(head_w + (size_t)(h0 + br) * TDIM + kc * 32 + bc4);
        }
    };
    auto conv_chunk = [&]() {
#pragma unroll
        for (int it = 0; it < 4; it++) {
            int fa = it * 256 + tid;
            int ar = fa >> 5, ac4 = (fa & 31) << 2;
            uint32_t h01, l01, h23, l23;
            split2(ra[it].x, ra[it].y, h01, l01);
            split2(ra[it].z, ra[it].w, h23, l23);
            uint32_t off = (uint32_t)(ar * PPADA + ac4) * 2;
            *(uint2*)(smem + POFF_A + off)            = make_uint2(h01, h23);
            *(uint2*)(smem + POFF_A + PA_HALF + off)  = make_uint2(l01, l23);
            int br = fa >> 3, bc4 = (fa & 7) << 2;
            split2(rb[it].x, rb[it].y, h01, l01);
            split2(rb[it].z, rb[it].w, h23, l23);
            off = (uint32_t)(br * PPADB + bc4) * 2;
            *(uint2*)(smem + POFF_B + off)            = make_uint2(h01, h23);
            *(uint2*)(smem + POFF_B + PB_HALF + off)  = make_uint2(l01, l23);
        }
    };

    float sacc[16][4];
#pragma unroll
    for (int t = 0; t < 16; t++)
#pragma unroll
        for (int j = 0; j < 4; j++) sacc[t][j] = 0.f;

    ldg_chunk(0);
    for (int kc = 0; kc < 8; kc++) {
        conv_chunk();
        __syncthreads();
        if (kc < 7) ldg_chunk(kc + 1);

        const uint32_t ahi = sbase + POFF_A, alo = ahi + PA_HALF;
        const uint32_t bhi = sbase + POFF_B, blo = bhi + PB_HALF;
#pragma unroll
        for (int kk = 0; kk < 2; kk++) {
            uint32_t ah[4], al[4];
            uint32_t aoff = a_off + (uint32_t)(kk * 16 * PPADA) * 2;
            ldsm4t(ah, ahi + aoff);
            ldsm4t(al, alo + aoff);
#pragma unroll
            for (int pr = 0; pr < 4; pr++) {
                uint32_t bh0[4], bl0[4], bh1[4], bl1[4];
                uint32_t bo0 = b_off + (uint32_t)((2 * pr) * 16 * PPADB + kk * 16) * 2;
                uint32_t bo1 = b_off + (uint32_t)((2 * pr + 1) * 16 * PPADB + kk * 16) * 2;
                ldsm4(bh0, bhi + bo0);
                ldsm4(bh1, bhi + bo1);
                ldsm4(bl0, blo + bo0);
                ldsm4(bl1, blo + bo1);
                float* A0 = sacc[4 * pr + 0];
                float* A1 = sacc[4 * pr + 1];
                float* A2 = sacc[4 * pr + 2];
                float* A3 = sacc[4 * pr + 3];
                mma16816(A0, ah, bh0[0], bh0[1]);
                mma16816(A1, ah, bh0[2], bh0[3]);
                mma16816(A2, ah, bh1[0], bh1[1]);
                mma16816(A3, ah, bh1[2], bh1[3]);
                mma16816(A0, ah, bl0[0], bl0[1]);
                mma16816(A1, ah, bl0[2], bl0[3]);
                mma16816(A2, ah, bl1[0], bl1[1]);
                mma16816(A3, ah, bl1[2], bl1[3]);
                mma16816(A0, al, bh0[0], bh0[1]);
                mma16816(A1, al, bh0[2], bh0[3]);
                mma16816(A2, al, bh1[0], bh1[1]);
                mma16816(A3, al, bh1[2], bh1[3]);
            }
        }
        __syncthreads();
    }

    // ---- epilogue: stage D[m][h] fp32, then store both layouts ----
    float* stg = (float*)smem;
    const int rr = lid >> 2, qq = lid & 3;
#pragma unroll
    for (int t = 0; t < 16; t++) {
        int hcl = t * 8 + 2 * qq;
        int m   = wid * 16 + rr;
        stg[(size_t)m * PSTG + hcl]           = sacc[t][0];
        stg[(size_t)m * PSTG + hcl + 1]       = sacc[t][1];
        stg[(size_t)(m + 8) * PSTG + hcl]     = sacc[t][2];
        stg[(size_t)(m + 8) * PSTG + hcl + 1] = sacc[t][3];
    }
    __syncthreads();

    // WpT[b][m][h0+h] bf16 hi/lo: rows m, coalesced over h
#pragma unroll
    for (int it = 0; it < 16; it++) {
        int f = it * 256 + tid;
        int m = f >> 5, c4 = (f & 31) << 2;
        const float* s = stg + (size_t)m * PSTG + c4;
        uint32_t h01, l01, h23, l23;
        split2(s[0], s[1], h01, l01);
        split2(s[2], s[3], h23, l23);
        size_t base = ((size_t)b * MDIM + m) * HDIM + h0 + c4;
        *(uint2*)(g_WpT_hi + base) = make_uint2(h01, h23);
        *(uint2*)(g_WpT_lo + base) = make_uint2(l01, l23);
    }
    // Wp[b][h0+h][m] single fp16: rows h, coalesced over m
#pragma unroll
    for (int it = 0; it < 16; it++) {
        int f = it * 256 + tid;
        int h = f >> 5, m4 = (f & 31) << 2;
        float x0 = stg[(size_t)(m4 + 0) * PSTG + h];
        float x1 = stg[(size_t)(m4 + 1) * PSTG + h];
        float x2 = stg[(size_t)(m4 + 2) * PSTG + h];
        float x3 = stg[(size_t)(m4 + 3) * PSTG + h];
        uint32_t p01 = packh2(x0, x1), p23 = packh2(x2, x3);
        size_t base = ((size_t)b * HDIM + h0 + h) * MDIM + m4;
        *(uint2*)(g_Wp_f16 + base) = make_uint2(p01, p23);
    }
}

// ============================================================
// Kernel 2: fused scores -> softmax -> output.
// GEMM1: 3-split bf16 (unchanged, k-chunks 32, 16 chunks).
// GEMM2: single fp16 MMA (E fp16 x Wp fp16), h-chunks 64, 8 chunks.
// 3 CTAs/SM (smem 69632).
//
// SMEM union (bytes):
//   GEMM1: KB0 @0 (20480), KB1 @20480 (end 40960),
//          Q0 @40960 (9216), Q1 @50176            -> end 59392
//   GEMM2: WB0 @0 (17408 fp16), WB1 @17408 (end 34816),
//          STG0 @34816 (17408), STG1 @52224       -> end 69632
// ============================================================
#define PADQ 72
#define PADK 40
#define PADW 136
#define STGS 68
#define OFF_KB  0
#define KB_SZ   20480
#define OFF_Q   40960
#define Q_SZ    9216
#define OFF_WB  0
#define WB_SZ   17408
#define OFF_STG 34816
#define STG_SZ  17408
#define SMEM_DYN 69632

__global__ __launch_bounds__(128, 3)
void attn_kernel(const float* __restrict__ H, float* __restrict__ out) {
    extern __shared__ char smem[];
    const uint32_t sbase = smem_u32(smem);

    const int tid = threadIdx.x;
    const int wid = tid >> 5;
    const int lid = tid & 31;
    const int b   = blockIdx.y;
    const int n0  = blockIdx.x * 64;

    const float* Hb = H + (size_t)b * HDIM * NDIM + n0;
    const __nv_bfloat16* KTh = g_WpT_hi + (size_t)b * MDIM * HDIM;
    const __nv_bfloat16* KTl = g_WpT_lo + (size_t)b * MDIM * HDIM;
    const __half*        Wpf = g_Wp_f16 + (size_t)b * HDIM * MDIM;

    const int g  = lid >> 3, lr = lid & 7;
    const int arow = ((g & 2) ? 8 : 0) + lr;
    const int acol = wid * 16 + ((g & 1) ? 8 : 0);
    const uint32_t a_off = (uint32_t)(arow * PADQ + acol) * 2;
    const int brow = ((g >> 1) ? 8 : 0) + lr;
    const int bcol = (g & 1) ? 8 : 0;
    const uint32_t b_off_k = (uint32_t)(brow * PADK + bcol) * 2;
    const uint32_t b_off_w = (uint32_t)(brow * PADW + bcol) * 2;

    auto issue_k = [&](int hc, int p) {
        uint32_t dh = sbase + OFF_KB + p * KB_SZ;
        uint32_t dl = dh + 10240;
        int k0 = hc * 32;
#pragma unroll
        for (int it = 0; it < 4; it++) {
            int f = it * 128 + tid, m = f >> 2, c8 = (f & 3) << 3;
            uint32_t o = (uint32_t)(m * PADK + c8) * 2;
            CP_ASYNC16(dh + o, KTh + (size_t)m * HDIM + k0 + c8);
            CP_ASYNC16(dl + o, KTl + (size_t)m * HDIM + k0 + c8);
        }
    };
    // Wp fp16 tile [h=64][m=128], single stream
    auto issue_w = [&](int hc2, int p) {
        uint32_t dw = sbase + OFF_WB + p * WB_SZ;
#pragma unroll
        for (int it = 0; it < 8; it++) {
            int f = it * 128 + tid, hr = f >> 4, c8 = (f & 15) << 3;
            uint32_t o = (uint32_t)(hr * PADW + c8) * 2;
            CP_ASYNC16(dw + o, Wpf + (size_t)(hc2 * 64 + hr) * MDIM + c8);
        }
    };
    auto ldg_q = [&](int hc, float4* qv) {
#pragma unroll
        for (int it = 0; it < 4; it++) {
            int f = it * 128 + tid, hr = f >> 4, c4 = (f & 15) << 2;
            qv[it] = *(const float4*)(Hb + (size_t)(hc * 32 + hr) * NDIM + c4);
        }
    };
    auto conv_q = [&](const float4* qv, int q) {
        uint32_t base_h = OFF_Q + q * Q_SZ;
#pragma unroll
        for (int it = 0; it < 4; it++) {
            int f = it * 128 + tid, hr = f >> 4, c4 = (f & 15) << 2;
            uint32_t h01, l01, h23, l23;
            split2(qv[it].x, qv[it].y, h01, l01);
            split2(qv[it].z, qv[it].w, h23, l23);
            uint32_t off = (uint32_t)(hr * PADQ + c4) * 2;
            *(uint2*)(smem + base_h + off)        = make_uint2(h01, h23);
            *(uint2*)(smem + base_h + 4608 + off) = make_uint2(l01, l23);
        }
    };

    // ---------------- GEMM1 (unchanged numerics) ----------------
    float sacc[16][4];
#pragma unroll
    for (int t = 0; t < 16; t++)
#pragma unroll
        for (int j = 0; j < 4; j++) sacc[t][j] = 0.f;

    float4 qv[4];
    issue_k(0, 0); CP_COMMIT();
    ldg_q(0, qv);
    conv_q(qv, 0);
    ldg_q(1, qv);

    for (int hc = 0; hc < 16; hc++) {
        const int p = hc & 1;
        CP_WAIT(0);
        __syncthreads();
        if (hc < 15) {
            issue_k(hc + 1, p ^ 1); CP_COMMIT();
            conv_q(qv, p ^ 1);
        }
        if (hc < 14) ldg_q(hc + 2, qv);

        const uint32_t qhi = sbase + OFF_Q + p * Q_SZ;
        const uint32_t qlo = qhi + 4608;
        const uint32_t khi = sbase + OFF_KB + p * KB_SZ;
        const uint32_t klo = khi + 10240;
#pragma unroll
        for (int kk = 0; kk < 2; kk++) {
            uint32_t ah[4], al[4];
            uint32_t aoff = a_off + (uint32_t)(kk * 16 * PADQ) * 2;
            ldsm4t(ah, qhi + aoff);
            ldsm4t(al, qlo + aoff);
#pragma unroll
            for (int pr = 0; pr < 4; pr++) {
                uint32_t bh0[4], bl0[4], bh1[4], bl1[4];
                uint32_t bo0 = b_off_k + (uint32_t)((2 * pr) * 16 * PADK + kk * 16) * 2;
                uint32_t bo1 = b_off_k + (uint32_t)((2 * pr + 1) * 16 * PADK + kk * 16) * 2;
                ldsm4(bh0, khi + bo0);
                ldsm4(bh1, khi + bo1);
                ldsm4(bl0, klo + bo0);
                ldsm4(bl1, klo + bo1);
                float* A0 = sacc[4 * pr + 0];
                float* A1 = sacc[4 * pr + 1];
                float* A2 = sacc[4 * pr + 2];
                float* A3 = sacc[4 * pr + 3];
                mma16816(A0, ah, bh0[0], bh0[1]);
                mma16816(A1, ah, bh0[2], bh0[3]);
                mma16816(A2, ah, bh1[0], bh1[1]);
                mma16816(A3, ah, bh1[2], bh1[3]);
                mma16816(A0, ah, bl0[0], bl0[1]);
                mma16816(A1, ah, bl0[2], bl0[3]);
                mma16816(A2, ah, bl1[0], bl1[1]);
                mma16816(A3, ah, bl1[2], bl1[3]);
                mma16816(A0, al, bh0[0], bh0[1]);
                mma16816(A1, al, bh0[2], bh0[3]);
                mma16816(A2, al, bh1[0], bh1[1]);
                mma16816(A3, al, bh1[2], bh1[3]);
            }
        }
    }

    // prefetch GEMM2 chunk 0 (WB0 @0..17408 aliases only dead KB0)
    issue_w(0, 0); CP_COMMIT();

    // ---------------- softmax over m (registers only) ----------------
    float mx0 = -3.4e38f, mx1 = -3.4e38f;
#pragma unroll
    for (int t = 0; t < 16; t++) {
        mx0 = fmaxf(mx0, fmaxf(sacc[t][0], sacc[t][1]));
        mx1 = fmaxf(mx1, fmaxf(sacc[t][2], sacc[t][3]));
    }
    mx0 = fmaxf(mx0, __shfl_xor_sync(0xFFFFFFFFu, mx0, 1));
    mx0 = fmaxf(mx0, __shfl_xor_sync(0xFFFFFFFFu, mx0, 2));
    mx1 = fmaxf(mx1, __shfl_xor_sync(0xFFFFFFFFu, mx1, 1));
    mx1 = fmaxf(mx1, __shfl_xor_sync(0xFFFFFFFFu, mx1, 2));
    float s0 = 0.f, s1 = 0.f;
#pragma unroll
    for (int t = 0; t < 16; t++) {
        sacc[t][0] = __expf(sacc[t][0] - mx0);
        sacc[t][1] = __expf(sacc[t][1] - mx0);
        sacc[t][2] = __expf(sacc[t][2] - mx1);
        sacc[t][3] = __expf(sacc[t][3] - mx1);
        s0 += sacc[t][0] + sacc[t][1];
        s1 += sacc[t][2] + sacc[t][3];
    }
    s0 += __shfl_xor_sync(0xFFFFFFFFu, s0, 1);
    s0 += __shfl_xor_sync(0xFFFFFFFFu, s0, 2);
    s1 += __shfl_xor_sync(0xFFFFFFFFu, s1, 1);
    s1 += __shfl_xor_sync(0xFFFFFFFFu, s1, 2);
    const float r0 = 1.0f / s0, r1 = 1.0f / s1;

    // Repack unnormalized E into fp16 A-fragments (k = m).
    uint32_t ef[8][4];
#pragma unroll
    for (int kk = 0; kk < 8; kk++) {
        int t0 = kk * 2;
        ef[kk][0] = packh2(sacc[t0][0],     sacc[t0][1]);
        ef[kk][1] = packh2(sacc[t0][2],     sacc[t0][3]);
        ef[kk][2] = packh2(sacc[t0 + 1][0], sacc[t0 + 1][1]);
        ef[kk][3] = packh2(sacc[t0 + 1][2], sacc[t0 + 1][3]);
    }

    // -------- GEMM2: C[n][h] = sum_m E[n][m] * Wp[h][m], fp16 x fp16 --------
    float* outb = out + (size_t)b * HDIM * NDIM;
    const int rr = lid >> 2, qq = lid & 3;

    for (int hc2 = 0; hc2 < 8; hc2++) {
        const int p = hc2 & 1;
        CP_WAIT(0);
        __syncthreads();                 // WB[p] visible; STG[p] free
        if (hc2 < 7) { issue_w(hc2 + 1, p ^ 1); CP_COMMIT(); }

        float cacc[8][4];
#pragma unroll
        for (int t = 0; t < 8; t++)
#pragma unroll
            for (int j = 0; j < 4; j++) cacc[t][j] = 0.f;

        const uint32_t wb = sbase + OFF_WB + p * WB_SZ;
#pragma unroll
        for (int kk = 0; kk < 8; kk++) {
            uint32_t b0[4], b1[4], b2[4], b3[4];
            uint32_t ko = (uint32_t)(kk * 16) * 2;
            ldsm4(b0, wb + b_off_w + ko);
            ldsm4(b1, wb + b_off_w + (uint32_t)(16 * PADW) * 2 + ko);
            ldsm4(b2, wb + b_off_w + (uint32_t)(32 * PADW) * 2 + ko);
            ldsm4(b3, wb + b_off_w + (uint32_t)(48 * PADW) * 2 + ko);
            mma16816f(cacc[0], ef[kk], b0[0], b0[1]);
            mma16816f(cacc[1], ef[kk], b0[2], b0[3]);
            mma16816f(cacc[2], ef[kk], b1[0], b1[1]);
            mma16816f(cacc[3], ef[kk], b1[2], b1[3]);
            mma16816f(cacc[4], ef[kk], b2[0], b2[1]);
            mma16816f(cacc[5], ef[kk], b2[2], b2[3]);
            mma16816f(cacc[6], ef[kk], b3[0], b3[1]);
            mma16816f(cacc[7], ef[kk], b3[2], b3[3]);
        }

        // scale by 1/sum and stage transposed into STG[p]: stg[h_local][n]
        float* stg = (float*)(smem + OFF_STG + p * STG_SZ);
#pragma unroll
        for (int t = 0; t < 8; t++) {
            int hcl = t * 8 + 2 * qq;
            int n   = wid * 16 + rr;
            stg[(size_t)hcl * STGS + n]           = cacc[t][0] * r0;
            stg[(size_t)(hcl + 1) * STGS + n]     = cacc[t][1] * r0;
            stg[(size_t)hcl * STGS + n + 8]       = cacc[t][2] * r1;
            stg[(size_t)(hcl + 1) * STGS + n + 8] = cacc[t][3] * r1;
        }
        __syncthreads();                 // stage writes visible

        // coalesced fp32 store: out[b][hc2*64+hr][n0 + ...]
#pragma unroll
        for (int it = 0; it < 8; it++) {
            int f = it * 128 + tid, hr = f >> 4, n4 = (f & 15) << 2;
            float4 v = *(const float4*)(stg + (size_t)hr * STGS + n4);
            *(float4*)(outb + (size_t)(hc2 * 64 + hr) * NDIM + n0 + n4) = v;
        }
        // no end barrier: STG[p] reused only in hc2+2, after the next top-sync
    }
}

// ============================================================
extern "C" void kernel_launch(void* const* d_in, const int* in_sizes, int n_in,
                              void* d_out, int out_size) {
    const float* H      = (const float*)d_in[0];  // [32,512,64,64]
    const float* W      = (const float*)d_in[1];  // [32,256,128]
    const float* head_w = (const float*)d_in[2];  // [512,256]
    float* out = (float*)d_out;

    cudaFuncSetAttribute(proj_kernel,
                         cudaFuncAttributeMaxDynamicSharedMemorySize, PSMEM);
    cudaFuncSetAttribute(attn_kernel,
                         cudaFuncAttributeMaxDynamicSharedMemorySize, SMEM_DYN);

    proj_kernel<<<dim3(4, B_DIM), 256, PSMEM>>>(W, head_w);
    attn_kernel<<<dim3(NDIM / 64, B_DIM), 128, SMEM_DYN>>>(H, out);
}

// round 13
// speedup vs baseline: 1.7495x; 1.0429x over previous
#include <cuda_runtime.h>
#include <cuda_bf16.h>
#include <cuda_fp16.h>
#include <cstdint>
#include <cstddef>

#define B_DIM 32
#define HDIM  512
#define NDIM  4096
#define MDIM  128
#define TDIM  256

// __device__ scratch. WpT bf16 hi/lo (GEMM1, 3-split); Wp single fp16 (GEMM2).
__device__ __align__(16) __nv_bfloat16 g_WpT_hi[B_DIM * MDIM * HDIM]; // [b][m][h]
__device__ __align__(16) __nv_bfloat16 g_WpT_lo[B_DIM * MDIM * HDIM];
__device__ __align__(16) __half        g_Wp_f16[B_DIM * HDIM * MDIM]; // [b][h][m]

// ---------------- helpers (all non-arch-specific PTX) ----------------
__device__ __forceinline__ uint32_t smem_u32(const void* p) {
    uint32_t a;
    asm("{ .reg .u64 t; cvta.to.shared.u64 t, %1; cvt.u32.u64 %0, t; }"
        : "=r"(a) : "l"(p));
    return a;
}
__device__ __forceinline__ void ldsm4(uint32_t* r, uint32_t a) {
    asm volatile("ldmatrix.sync.aligned.m8n8.x4.shared.b16 {%0,%1,%2,%3}, [%4];"
        : "=r"(r[0]), "=r"(r[1]), "=r"(r[2]), "=r"(r[3]) : "r"(a));
}
__device__ __forceinline__ void ldsm4t(uint32_t* r, uint32_t a) {
    asm volatile("ldmatrix.sync.aligned.m8n8.x4.trans.shared.b16 {%0,%1,%2,%3}, [%4];"
        : "=r"(r[0]), "=r"(r[1]), "=r"(r[2]), "=r"(r[3]) : "r"(a));
}
__device__ __forceinline__ void mma16816(float* d, const uint32_t* a,
                                         uint32_t b0, uint32_t b1) {
    asm volatile(
        "mma.sync.aligned.m16n8k16.row.col.f32.bf16.bf16.f32 "
        "{%0,%1,%2,%3}, {%4,%5,%6,%7}, {%8,%9}, {%0,%1,%2,%3};"
        : "+f"(d[0]), "+f"(d[1]), "+f"(d[2]), "+f"(d[3])
        : "r"(a[0]), "r"(a[1]), "r"(a[2]), "r"(a[3]), "r"(b0), "r"(b1));
}
__device__ __forceinline__ void mma16816f(float* d, const uint32_t* a,
                                          uint32_t b0, uint32_t b1) {
    asm volatile(
        "mma.sync.aligned.m16n8k16.row.col.f32.f16.f16.f32 "
        "{%0,%1,%2,%3}, {%4,%5,%6,%7}, {%8,%9}, {%0,%1,%2,%3};"
        : "+f"(d[0]), "+f"(d[1]), "+f"(d[2]), "+f"(d[3])
        : "r"(a[0]), "r"(a[1]), "r"(a[2]), "r"(a[3]), "r"(b0), "r"(b1));
}
__device__ __forceinline__ void split2(float x, float y, uint32_t& hi, uint32_t& lo) {
    __nv_bfloat16 xh = __float2bfloat16(x);
    __nv_bfloat16 yh = __float2bfloat16(y);
    __nv_bfloat16 xl = __float2bfloat16(x - __bfloat162float(xh));
    __nv_bfloat16 yl = __float2bfloat16(y - __bfloat162float(yh));
    hi = (uint32_t)__bfloat16_as_ushort(xh) | ((uint32_t)__bfloat16_as_ushort(yh) << 16);
    lo = (uint32_t)__bfloat16_as_ushort(xl) | ((uint32_t)__bfloat16_as_ushort(yl) << 16);
}
__device__ __forceinline__ uint32_t packh2(float x, float y) {
    __half2 h = __floats2half2_rn(x, y);
    return *(uint32_t*)&h;
}
#define CP_ASYNC16(dst, src)                                                   \
    asm volatile("cp.async.cg.shared.global [%0], [%1], 16;"                   \
                 :: "r"(dst), "l"(src))
#define CP_COMMIT() asm volatile("cp.async.commit_group;" ::: "memory")
#define CP_WAIT(n)  asm volatile("cp.async.wait_group %0;" :: "n"(n) : "memory")

// ============================================================
// Kernel 1 (unchanged from R12): WpT bf16 hi/lo + Wp fp16 via 3-split MMA.
//   D[m][h] = sum_t W[b][t][m] * head_w[h0+h][t]
// Grid (4, 32), 256 threads = 8 warps x 16 m-rows.
// ============================================================
#define PPADA 136
#define PPADB 40
#define PSTG  133
#define POFF_A  0
#define PA_HALF 8704
#define POFF_B  17408
#define PB_HALF 10240
#define PSMEM   69632

__global__ __launch_bounds__(256) void proj_kernel(const float* __restrict__ W,
                                                   const float* __restrict__ head_w) {
    extern __shared__ char smem[];
    const uint32_t sbase = smem_u32(smem);

    const int tid = threadIdx.x;
    const int wid = tid >> 5;
    const int lid = tid & 31;
    const int b   = blockIdx.y;
    const int h0  = blockIdx.x * 128;

    const float* Wb = W + (size_t)b * TDIM * MDIM;

    const int g  = lid >> 3, lr = lid & 7;
    const int arow = ((g & 2) ? 8 : 0) + lr;
    const int acol = wid * 16 + ((g & 1) ? 8 : 0);
    const uint32_t a_off = (uint32_t)(arow * PPADA + acol) * 2;
    const int brow = ((g >> 1) ? 8 : 0) + lr;
    const int bcol = (g & 1) ? 8 : 0;
    const uint32_t b_off = (uint32_t)(brow * PPADB + bcol) * 2;

    float4 ra[4], rb[4];
    auto ldg_chunk = [&](int kc) {
#pragma unroll
        for (int it = 0; it < 4; it++) {
            int fa = it * 256 + tid;
            int ar = fa >> 5, ac4 = (fa & 31) << 2;
            ra[it] = *(const float4*)(Wb + (size_t)(kc * 32 + ar) * MDIM + ac4);
            int br = fa >> 3, bc4 = (fa & 7) << 2;
            rb[it] = *(const float4*)(head_w + (size_t)(h0 + br) * TDIM + kc * 32 + bc4);
        }
    };
    auto conv_chunk = [&]() {
#pragma unroll
        for (int it = 0; it < 4; it++) {
            int fa = it * 256 + tid;
            int ar = fa >> 5, ac4 = (fa & 31) << 2;
            uint32_t h01, l01, h23, l23;
            split2(ra[it].x, ra[it].y, h01, l01);
            split2(ra[it].z, ra[it].w, h23, l23);
            uint32_t off = (uint32_t)(ar * PPADA + ac4) * 2;
            *(uint2*)(smem + POFF_A + off)            = make_uint2(h01, h23);
            *(uint2*)(smem + POFF_A + PA_HALF + off)  = make_uint2(l01, l23);
            int br = fa >> 3, bc4 = (fa & 7) << 2;
            split2(rb[it].x, rb[it].y, h01, l01);
            split2(rb[it].z, rb[it].w, h23, l23);
            off = (uint32_t)(br * PPADB + bc4) * 2;
            *(uint2*)(smem + POFF_B + off)            = make_uint2(h01, h23);
            *(uint2*)(smem + POFF_B + PB_HALF + off)  = make_uint2(l01, l23);
        }
    };

    float sacc[16][4];
#pragma unroll
    for (int t = 0; t < 16; t++)
#pragma unroll
        for (int j = 0; j < 4; j++) sacc[t][j] = 0.f;

    ldg_chunk(0);
    for (int kc = 0; kc < 8; kc++) {
        conv_chunk();
        __syncthreads();
        if (kc < 7) ldg_chunk(kc + 1);

        const uint32_t ahi = sbase + POFF_A, alo = ahi + PA_HALF;
        const uint32_t bhi = sbase + POFF_B, blo = bhi + PB_HALF;
#pragma unroll
        for (int kk = 0; kk < 2; kk++) {
            uint32_t ah[4], al[4];
            uint32_t aoff = a_off + (uint32_t)(kk * 16 * PPADA) * 2;
            ldsm4t(ah, ahi + aoff);
            ldsm4t(al, alo + aoff);
#pragma unroll
            for (int pr = 0; pr < 4; pr++) {
                uint32_t bh0[4], bl0[4], bh1[4], bl1[4];
                uint32_t bo0 = b_off + (uint32_t)((2 * pr) * 16 * PPADB + kk * 16) * 2;
                uint32_t bo1 = b_off + (uint32_t)((2 * pr + 1) * 16 * PPADB + kk * 16) * 2;
                ldsm4(bh0, bhi + bo0);
                ldsm4(bh1, bhi + bo1);
                ldsm4(bl0, blo + bo0);
                ldsm4(bl1, blo + bo1);
                float* A0 = sacc[4 * pr + 0];
                float* A1 = sacc[4 * pr + 1];
                float* A2 = sacc[4 * pr + 2];
                float* A3 = sacc[4 * pr + 3];
                mma16816(A0, ah, bh0[0], bh0[1]);
                mma16816(A1, ah, bh0[2], bh0[3]);
                mma16816(A2, ah, bh1[0], bh1[1]);
                mma16816(A3, ah, bh1[2], bh1[3]);
                mma16816(A0, ah, bl0[0], bl0[1]);
                mma16816(A1, ah, bl0[2], bl0[3]);
                mma16816(A2, ah, bl1[0], bl1[1]);
                mma16816(A3, ah, bl1[2], bl1[3]);
                mma16816(A0, al, bh0[0], bh0[1]);
                mma16816(A1, al, bh0[2], bh0[3]);
                mma16816(A2, al, bh1[0], bh1[1]);
                mma16816(A3, al, bh1[2], bh1[3]);
            }
        }
        __syncthreads();
    }

    // ---- epilogue: stage D[m][h] fp32, then store both layouts ----
    float* stg = (float*)smem;
    const int rr = lid >> 2, qq = lid & 3;
#pragma unroll
    for (int t = 0; t < 16; t++) {
        int hcl = t * 8 + 2 * qq;
        int m   = wid * 16 + rr;
        stg[(size_t)m * PSTG + hcl]           = sacc[t][0];
        stg[(size_t)m * PSTG + hcl + 1]       = sacc[t][1];
        stg[(size_t)(m + 8) * PSTG + hcl]     = sacc[t][2];
        stg[(size_t)(m + 8) * PSTG + hcl + 1] = sacc[t][3];
    }
    __syncthreads();

#pragma unroll
    for (int it = 0; it < 16; it++) {
        int f = it * 256 + tid;
        int m = f >> 5, c4 = (f & 31) << 2;
        const float* s = stg + (size_t)m * PSTG + c4;
        uint32_t h01, l01, h23, l23;
        split2(s[0], s[1], h01, l01);
        split2(s[2], s[3], h23, l23);
        size_t base = ((size_t)b * MDIM + m) * HDIM + h0 + c4;
        *(uint2*)(g_WpT_hi + base) = make_uint2(h01, h23);
        *(uint2*)(g_WpT_lo + base) = make_uint2(l01, l23);
    }
#pragma unroll
    for (int it = 0; it < 16; it++) {
        int f = it * 256 + tid;
        int h = f >> 5, m4 = (f & 31) << 2;
        float x0 = stg[(size_t)(m4 + 0) * PSTG + h];
        float x1 = stg[(size_t)(m4 + 1) * PSTG + h];
        float x2 = stg[(size_t)(m4 + 2) * PSTG + h];
        float x3 = stg[(size_t)(m4 + 3) * PSTG + h];
        uint32_t p01 = packh2(x0, x1), p23 = packh2(x2, x3);
        size_t base = ((size_t)b * HDIM + h0 + h) * MDIM + m4;
        *(uint2*)(g_Wp_f16 + base) = make_uint2(p01, p23);
    }
}

// ============================================================
// Kernel 2: fused scores -> softmax -> output.
// NOW 4 CTAs/SM (16 warps): regs capped at 128 via launch_bounds(128,4),
// smem 52224 B. Q single-buffered (2 barriers/GEMM1 chunk, hidden by
// cross-CTA overlap). GEMM2 single staging buffer. Numerics identical
// to R12 (GEMM1 3-split bf16, GEMM2 single fp16).
//
// SMEM union (bytes):
//   GEMM1: KB0 @0 (20480), KB1 @20480 (end 40960), Q @40960 (9216) -> 50176
//   GEMM2: WB0 @0 (17408), WB1 @17408 (end 34816), STG @34816 (17408) -> 52224
// ============================================================
#define PADQ 72
#define PADK 40
#define PADW 136
#define STGS 68
#define OFF_KB  0
#define KB_SZ   20480
#define OFF_Q   40960
#define OFF_WB  0
#define WB_SZ   17408
#define OFF_STG 34816
#define SMEM_DYN 52224

__global__ __launch_bounds__(128, 4)
void attn_kernel(const float* __restrict__ H, float* __restrict__ out) {
    extern __shared__ char smem[];
    const uint32_t sbase = smem_u32(smem);

    const int tid = threadIdx.x;
    const int wid = tid >> 5;
    const int lid = tid & 31;
    const int b   = blockIdx.y;
    const int n0  = blockIdx.x * 64;

    const float* Hb = H + (size_t)b * HDIM * NDIM + n0;
    const __nv_bfloat16* KTh = g_WpT_hi + (size_t)b * MDIM * HDIM;
    const __nv_bfloat16* KTl = g_WpT_lo + (size_t)b * MDIM * HDIM;
    const __half*        Wpf = g_Wp_f16 + (size_t)b * HDIM * MDIM;

    const int g  = lid >> 3, lr = lid & 7;
    const int arow = ((g & 2) ? 8 : 0) + lr;
    const int acol = wid * 16 + ((g & 1) ? 8 : 0);
    const uint32_t a_off = (uint32_t)(arow * PADQ + acol) * 2;
    const int brow = ((g >> 1) ? 8 : 0) + lr;
    const int bcol = (g & 1) ? 8 : 0;
    const uint32_t b_off_k = (uint32_t)(brow * PADK + bcol) * 2;
    const uint32_t b_off_w = (uint32_t)(brow * PADW + bcol) * 2;

    auto issue_k = [&](int hc, int p) {
        uint32_t dh = sbase + OFF_KB + p * KB_SZ;
        uint32_t dl = dh + 10240;
        int k0 = hc * 32;
#pragma unroll
        for (int it = 0; it < 4; it++) {
            int f = it * 128 + tid, m = f >> 2, c8 = (f & 3) << 3;
            uint32_t o = (uint32_t)(m * PADK + c8) * 2;
            CP_ASYNC16(dh + o, KTh + (size_t)m * HDIM + k0 + c8);
            CP_ASYNC16(dl + o, KTl + (size_t)m * HDIM + k0 + c8);
        }
    };
    auto issue_w = [&](int hc2, int p) {
        uint32_t dw = sbase + OFF_WB + p * WB_SZ;
#pragma unroll
        for (int it = 0; it < 8; it++) {
            int f = it * 128 + tid, hr = f >> 4, c8 = (f & 15) << 3;
            uint32_t o = (uint32_t)(hr * PADW + c8) * 2;
            CP_ASYNC16(dw + o, Wpf + (size_t)(hc2 * 64 + hr) * MDIM + c8);
        }
    };
    auto ldg_q = [&](int hc, float4* qv) {
#pragma unroll
        for (int it = 0; it < 4; it++) {
            int f = it * 128 + tid, hr = f >> 4, c4 = (f & 15) << 2;
            qv[it] = *(const float4*)(Hb + (size_t)(hc * 32 + hr) * NDIM + c4);
        }
    };
    auto conv_q = [&](const float4* qv) {
#pragma unroll
        for (int it = 0; it < 4; it++) {
            int f = it * 128 + tid, hr = f >> 4, c4 = (f & 15) << 2;
            uint32_t h01, l01, h23, l23;
            split2(qv[it].x, qv[it].y, h01, l01);
            split2(qv[it].z, qv[it].w, h23, l23);
            uint32_t off = (uint32_t)(hr * PADQ + c4) * 2;
            *(uint2*)(smem + OFF_Q + off)        = make_uint2(h01, h23);
            *(uint2*)(smem + OFF_Q + 4608 + off) = make_uint2(l01, l23);
        }
    };

    // ---------------- GEMM1 (numerics unchanged) ----------------
    float sacc[16][4];
#pragma unroll
    for (int t = 0; t < 16; t++)
#pragma unroll
        for (int j = 0; j < 4; j++) sacc[t][j] = 0.f;

    float4 qv[4];
    issue_k(0, 0); CP_COMMIT();
    ldg_q(0, qv);
    conv_q(qv);                  // Q for chunk 0 (visible at first sync)
    ldg_q(1, qv);

    for (int hc = 0; hc < 16; hc++) {
        const int p = hc & 1;
        CP_WAIT(0);
        __syncthreads();                 // K[p] + Q(chunk hc) visible
        if (hc < 15) { issue_k(hc + 1, p ^ 1); CP_COMMIT(); }

        const uint32_t qhi = sbase + OFF_Q;
        const uint32_t qlo = qhi + 4608;
        const uint32_t khi = sbase + OFF_KB + p * KB_SZ;
        const uint32_t klo = khi + 10240;
#pragma unroll
        for (int kk = 0; kk < 2; kk++) {
            uint32_t ah[4], al[4];
            uint32_t aoff = a_off + (uint32_t)(kk * 16 * PADQ) * 2;
            ldsm4t(ah, qhi + aoff);
            ldsm4t(al, qlo + aoff);
#pragma unroll
            for (int pr = 0; pr < 4; pr++) {
                uint32_t bh0[4], bl0[4], bh1[4], bl1[4];
                uint32_t bo0 = b_off_k + (uint32_t)((2 * pr) * 16 * PADK + kk * 16) * 2;
                uint32_t bo1 = b_off_k + (uint32_t)((2 * pr + 1) * 16 * PADK + kk * 16) * 2;
                ldsm4(bh0, khi + bo0);
                ldsm4(bh1, khi + bo1);
                ldsm4(bl0, klo + bo0);
                ldsm4(bl1, klo + bo1);
                float* A0 = sacc[4 * pr + 0];
                float* A1 = sacc[4 * pr + 1];
                float* A2 = sacc[4 * pr + 2];
                float* A3 = sacc[4 * pr + 3];
                mma16816(A0, ah, bh0[0], bh0[1]);
                mma16816(A1, ah, bh0[2], bh0[3]);
                mma16816(A2, ah, bh1[0], bh1[1]);
                mma16816(A3, ah, bh1[2], bh1[3]);
                mma16816(A0, ah, bl0[0], bl0[1]);
                mma16816(A1, ah, bl0[2], bl0[3]);
                mma16816(A2, ah, bl1[0], bl1[1]);
                mma16816(A3, ah, bl1[2], bl1[3]);
                mma16816(A0, al, bh0[0], bh0[1]);
                mma16816(A1, al, bh0[2], bh0[3]);
                mma16816(A2, al, bh1[0], bh1[1]);
                mma16816(A3, al, bh1[2], bh1[3]);
            }
        }
        __syncthreads();                 // all warps done reading Q buffer
        if (hc < 15) conv_q(qv);         // write Q for chunk hc+1
        if (hc < 14) ldg_q(hc + 2, qv);
    }

    // prefetch GEMM2 chunk 0 (WB0 @0..17408 aliases only dead KB0)
    issue_w(0, 0); CP_COMMIT();

    // ---------------- softmax over m (registers only) ----------------
    float mx0 = -3.4e38f, mx1 = -3.4e38f;
#pragma unroll
    for (int t = 0; t < 16; t++) {
        mx0 = fmaxf(mx0, fmaxf(sacc[t][0], sacc[t][1]));
        mx1 = fmaxf(mx1, fmaxf(sacc[t][2], sacc[t][3]));
    }
    mx0 = fmaxf(mx0, __shfl_xor_sync(0xFFFFFFFFu, mx0, 1));
    mx0 = fmaxf(mx0, __shfl_xor_sync(0xFFFFFFFFu, mx0, 2));
    mx1 = fmaxf(mx1, __shfl_xor_sync(0xFFFFFFFFu, mx1, 1));
    mx1 = fmaxf(mx1, __shfl_xor_sync(0xFFFFFFFFu, mx1, 2));
    float s0 = 0.f, s1 = 0.f;
#pragma unroll
    for (int t = 0; t < 16; t++) {
        sacc[t][0] = __expf(sacc[t][0] - mx0);
        sacc[t][1] = __expf(sacc[t][1] - mx0);
        sacc[t][2] = __expf(sacc[t][2] - mx1);
        sacc[t][3] = __expf(sacc[t][3] - mx1);
        s0 += sacc[t][0] + sacc[t][1];
        s1 += sacc[t][2] + sacc[t][3];
    }
    s0 += __shfl_xor_sync(0xFFFFFFFFu, s0, 1);
    s0 += __shfl_xor_sync(0xFFFFFFFFu, s0, 2);
    s1 += __shfl_xor_sync(0xFFFFFFFFu, s1, 1);
    s1 += __shfl_xor_sync(0xFFFFFFFFu, s1, 2);
    const float r0 = 1.0f / s0, r1 = 1.0f / s1;

    // Repack unnormalized E into fp16 A-fragments (k = m).
    uint32_t ef[8][4];
#pragma unroll
    for (int kk = 0; kk < 8; kk++) {
        int t0 = kk * 2;
        ef[kk][0] = packh2(sacc[t0][0],     sacc[t0][1]);
        ef[kk][1] = packh2(sacc[t0][2],     sacc[t0][3]);
        ef[kk][2] = packh2(sacc[t0 + 1][0], sacc[t0 + 1][1]);
        ef[kk][3] = packh2(sacc[t0 + 1][2], sacc[t0 + 1][3]);
    }

    // -------- GEMM2: C[n][h] = sum_m E[n][m] * Wp[h][m], fp16 x fp16 --------
    float* outb = out + (size_t)b * HDIM * NDIM;
    const int rr = lid >> 2, qq = lid & 3;
    float* stg = (float*)(smem + OFF_STG);

    for (int hc2 = 0; hc2 < 8; hc2++) {
        const int p = hc2 & 1;
        CP_WAIT(0);
        __syncthreads();                 // WB[p] visible; STG free (stores done)
        if (hc2 < 7) { issue_w(hc2 + 1, p ^ 1); CP_COMMIT(); }

        float cacc[8][4];
#pragma unroll
        for (int t = 0; t < 8; t++)
#pragma unroll
            for (int j = 0; j < 4; j++) cacc[t][j] = 0.f;

        const uint32_t wb = sbase + OFF_WB + p * WB_SZ;
#pragma unroll
        for (int kk = 0; kk < 8; kk++) {
            uint32_t b0[4], b1[4], b2[4], b3[4];
            uint32_t ko = (uint32_t)(kk * 16) * 2;
            ldsm4(b0, wb + b_off_w + ko);
            ldsm4(b1, wb + b_off_w + (uint32_t)(16 * PADW) * 2 + ko);
            ldsm4(b2, wb + b_off_w + (uint32_t)(32 * PADW) * 2 + ko);
            ldsm4(b3, wb + b_off_w + (uint32_t)(48 * PADW) * 2 + ko);
            mma16816f(cacc[0], ef[kk], b0[0], b0[1]);
            mma16816f(cacc[1], ef[kk], b0[2], b0[3]);
            mma16816f(cacc[2], ef[kk], b1[0], b1[1]);
            mma16816f(cacc[3], ef[kk], b1[2], b1[3]);
            mma16816f(cacc[4], ef[kk], b2[0], b2[1]);
            mma16816f(cacc[5], ef[kk], b2[2], b2[3]);
            mma16816f(cacc[6], ef[kk], b3[0], b3[1]);
            mma16816f(cacc[7], ef[kk], b3[2], b3[3]);
        }

        // scale by 1/sum and stage transposed: stg[h_local][n]
#pragma unroll
        for (int t = 0; t < 8; t++) {
            int hcl = t * 8 + 2 * qq;
            int n   = wid * 16 + rr;
            stg[(size_t)hcl * STGS + n]           = cacc[t][0] * r0;
            stg[(size_t)(hcl + 1) * STGS + n]     = cacc[t][1] * r0;
            stg[(size_t)hcl * STGS + n + 8]       = cacc[t][2] * r1;
            stg[(size_t)(hcl + 1) * STGS + n + 8] = cacc[t][3] * r1;
        }
        __syncthreads();                 // stage writes visible

        // coalesced fp32 store: out[b][hc2*64+hr][n0 + ...]
#pragma unroll
        for (int it = 0; it < 8; it++) {
            int f = it * 128 + tid, hr = f >> 4, n4 = (f & 15) << 2;
            float4 v = *(const float4*)(stg + (size_t)hr * STGS + n4);
            *(float4*)(outb + (size_t)(hc2 * 64 + hr) * NDIM + n0 + n4) = v;
        }
        // STG reuse protected by the next chunk's top __syncthreads()
    }
}

// ============================================================
extern "C" void kernel_launch(void* const* d_in, const int* in_sizes, int n_in,
                              void* d_out, int out_size) {
    const float* H      = (const float*)d_in[0];  // [32,512,64,64]
    const float* W      = (const float*)d_in[1];  // [32,256,128]
    const float* head_w = (const float*)d_in[2];  // [512,256]
    float* out = (float*)d_out;

    cudaFuncSetAttribute(proj_kernel,
                         cudaFuncAttributeMaxDynamicSharedMemorySize, PSMEM);
    cudaFuncSetAttribute(attn_kernel,
                         cudaFuncAttributeMaxDynamicSharedMemorySize, SMEM_DYN);

    proj_kernel<<<dim3(4, B_DIM), 256, PSMEM>>>(W, head_w);
    attn_kernel<<<dim3(NDIM / 64, B_DIM), 128, SMEM_DYN>>>(H, out);
}

// round 14
// speedup vs baseline: 1.8082x; 1.0335x over previous
#include <cuda_runtime.h>
#include <cuda_bf16.h>
#include <cuda_fp16.h>
#include <cstdint>
#include <cstddef>

#define B_DIM 32
#define HDIM  512
#define NDIM  4096
#define MDIM  128
#define TDIM  256

// __device__ scratch. WpT bf16 hi/lo (GEMM1, 3-split); Wp single fp16 (GEMM2).
__device__ __align__(16) __nv_bfloat16 g_WpT_hi[B_DIM * MDIM * HDIM]; // [b][m][h]
__device__ __align__(16) __nv_bfloat16 g_WpT_lo[B_DIM * MDIM * HDIM];
__device__ __align__(16) __half        g_Wp_f16[B_DIM * HDIM * MDIM]; // [b][h][m]

// ---------------- helpers (all non-arch-specific PTX) ----------------
__device__ __forceinline__ uint32_t smem_u32(const void* p) {
    uint32_t a;
    asm("{ .reg .u64 t; cvta.to.shared.u64 t, %1; cvt.u32.u64 %0, t; }"
        : "=r"(a) : "l"(p));
    return a;
}
__device__ __forceinline__ void ldsm4(uint32_t* r, uint32_t a) {
    asm volatile("ldmatrix.sync.aligned.m8n8.x4.shared.b16 {%0,%1,%2,%3}, [%4];"
        : "=r"(r[0]), "=r"(r[1]), "=r"(r[2]), "=r"(r[3]) : "r"(a));
}
__device__ __forceinline__ void ldsm4t(uint32_t* r, uint32_t a) {
    asm volatile("ldmatrix.sync.aligned.m8n8.x4.trans.shared.b16 {%0,%1,%2,%3}, [%4];"
        : "=r"(r[0]), "=r"(r[1]), "=r"(r[2]), "=r"(r[3]) : "r"(a));
}
__device__ __forceinline__ void mma16816(float* d, const uint32_t* a,
                                         uint32_t b0, uint32_t b1) {
    asm volatile(
        "mma.sync.aligned.m16n8k16.row.col.f32.bf16.bf16.f32 "
        "{%0,%1,%2,%3}, {%4,%5,%6,%7}, {%8,%9}, {%0,%1,%2,%3};"
        : "+f"(d[0]), "+f"(d[1]), "+f"(d[2]), "+f"(d[3])
        : "r"(a[0]), "r"(a[1]), "r"(a[2]), "r"(a[3]), "r"(b0), "r"(b1));
}
__device__ __forceinline__ void mma16816f(float* d, const uint32_t* a,
                                          uint32_t b0, uint32_t b1) {
    asm volatile(
        "mma.sync.aligned.m16n8k16.row.col.f32.f16.f16.f32 "
        "{%0,%1,%2,%3}, {%4,%5,%6,%7}, {%8,%9}, {%0,%1,%2,%3};"
        : "+f"(d[0]), "+f"(d[1]), "+f"(d[2]), "+f"(d[3])
        : "r"(a[0]), "r"(a[1]), "r"(a[2]), "r"(a[3]), "r"(b0), "r"(b1));
}
__device__ __forceinline__ void split2(float x, float y, uint32_t& hi, uint32_t& lo) {
    __nv_bfloat16 xh = __float2bfloat16(x);
    __nv_bfloat16 yh = __float2bfloat16(y);
    __nv_bfloat16 xl = __float2bfloat16(x - __bfloat162float(xh));
    __nv_bfloat16 yl = __float2bfloat16(y - __bfloat162float(yh));
    hi = (uint32_t)__bfloat16_as_ushort(xh) | ((uint32_t)__bfloat16_as_ushort(yh) << 16);
    lo = (uint32_t)__bfloat16_as_ushort(xl) | ((uint32_t)__bfloat16_as_ushort(yl) << 16);
}
__device__ __forceinline__ uint32_t packh2(float x, float y) {
    __half2 h = __floats2half2_rn(x, y);
    return *(uint32_t*)&h;
}
#define CP_ASYNC16(dst, src)                                                   \
    asm volatile("cp.async.cg.shared.global [%0], [%1], 16;"                   \
                 :: "r"(dst), "l"(src))
#define CP_COMMIT() asm volatile("cp.async.commit_group;" ::: "memory")
#define CP_WAIT(n)  asm volatile("cp.async.wait_group %0;" :: "n"(n) : "memory")

// ============================================================
// Kernel 1 (unchanged from R12/R13): WpT bf16 hi/lo + Wp fp16.
// ============================================================
#define PPADA 136
#define PPADB 40
#define PSTG  133
#define POFF_A  0
#define PA_HALF 8704
#define POFF_B  17408
#define PB_HALF 10240
#define PSMEM   69632

__global__ __launch_bounds__(256) void proj_kernel(const float* __restrict__ W,
                                                   const float* __restrict__ head_w) {
    extern __shared__ char smem[];
    const uint32_t sbase = smem_u32(smem);

    const int tid = threadIdx.x;
    const int wid = tid >> 5;
    const int lid = tid & 31;
    const int b   = blockIdx.y;
    const int h0  = blockIdx.x * 128;

    const float* Wb = W + (size_t)b * TDIM * MDIM;

    const int g  = lid >> 3, lr = lid & 7;
    const int arow = ((g & 2) ? 8 : 0) + lr;
    const int acol = wid * 16 + ((g & 1) ? 8 : 0);
    const uint32_t a_off = (uint32_t)(arow * PPADA + acol) * 2;
    const int brow = ((g >> 1) ? 8 : 0) + lr;
    const int bcol = (g & 1) ? 8 : 0;
    const uint32_t b_off = (uint32_t)(brow * PPADB + bcol) * 2;

    float4 ra[4], rb[4];
    auto ldg_chunk = [&](int kc) {
#pragma unroll
        for (int it = 0; it < 4; it++) {
            int fa = it * 256 + tid;
            int ar = fa >> 5, ac4 = (fa & 31) << 2;
            ra[it] = *(const float4*)(Wb + (size_t)(kc * 32 + ar) * MDIM + ac4);
            int br = fa >> 3, bc4 = (fa & 7) << 2;
            rb[it] = *(const float4*)(head_w + (size_t)(h0 + br) * TDIM + kc * 32 + bc4);
        }
    };
    auto conv_chunk = [&]() {
#pragma unroll
        for (int it = 0; it < 4; it++) {
            int fa = it * 256 + tid;
            int ar = fa >> 5, ac4 = (fa & 31) << 2;
            uint32_t h01, l01, h23, l23;
            split2(ra[it].x, ra[it].y, h01, l01);
            split2(ra[it].z, ra[it].w, h23, l23);
            uint32_t off = (uint32_t)(ar * PPADA + ac4) * 2;
            *(uint2*)(smem + POFF_A + off)            = make_uint2(h01, h23);
            *(uint2*)(smem + POFF_A + PA_HALF + off)  = make_uint2(l01, l23);
            int br = fa >> 3, bc4 = (fa & 7) << 2;
            split2(rb[it].x, rb[it].y, h01, l01);
            split2(rb[it].z, rb[it].w, h23, l23);
            off = (uint32_t)(br * PPADB + bc4) * 2;
            *(uint2*)(smem + POFF_B + off)            = make_uint2(h01, h23);
            *(uint2*)(smem + POFF_B + PB_HALF + off)  = make_uint2(l01, l23);
        }
    };

    float sacc[16][4];
#pragma unroll
    for (int t = 0; t < 16; t++)
#pragma unroll
        for (int j = 0; j < 4; j++) sacc[t][j] = 0.f;

    ldg_chunk(0);
    for (int kc = 0; kc < 8; kc++) {
        conv_chunk();
        __syncthreads();
        if (kc < 7) ldg_chunk(kc + 1);

        const uint32_t ahi = sbase + POFF_A, alo = ahi + PA_HALF;
        const uint32_t bhi = sbase + POFF_B, blo = bhi + PB_HALF;
#pragma unroll
        for (int kk = 0; kk < 2; kk++) {
            uint32_t ah[4], al[4];
            uint32_t aoff = a_off + (uint32_t)(kk * 16 * PPADA) * 2;
            ldsm4t(ah, ahi + aoff);
            ldsm4t(al, alo + aoff);
#pragma unroll
            for (int pr = 0; pr < 4; pr++) {
                uint32_t bh0[4], bl0[4], bh1[4], bl1[4];
                uint32_t bo0 = b_off + (uint32_t)((2 * pr) * 16 * PPADB + kk * 16) * 2;
                uint32_t bo1 = b_off + (uint32_t)((2 * pr + 1) * 16 * PPADB + kk * 16) * 2;
                ldsm4(bh0, bhi + bo0);
                ldsm4(bh1, bhi + bo1);
                ldsm4(bl0, blo + bo0);
                ldsm4(bl1, blo + bo1);
                float* A0 = sacc[4 * pr + 0];
                float* A1 = sacc[4 * pr + 1];
                float* A2 = sacc[4 * pr + 2];
                float* A3 = sacc[4 * pr + 3];
                mma16816(A0, ah, bh0[0], bh0[1]);
                mma16816(A1, ah, bh0[2], bh0[3]);
                mma16816(A2, ah, bh1[0], bh1[1]);
                mma16816(A3, ah, bh1[2], bh1[3]);
                mma16816(A0, ah, bl0[0], bl0[1]);
                mma16816(A1, ah, bl0[2], bl0[3]);
                mma16816(A2, ah, bl1[0], bl1[1]);
                mma16816(A3, ah, bl1[2], bl1[3]);
                mma16816(A0, al, bh0[0], bh0[1]);
                mma16816(A1, al, bh0[2], bh0[3]);
                mma16816(A2, al, bh1[0], bh1[1]);
                mma16816(A3, al, bh1[2], bh1[3]);
            }
        }
        __syncthreads();
    }

    float* stg = (float*)smem;
    const int rr = lid >> 2, qq = lid & 3;
#pragma unroll
    for (int t = 0; t < 16; t++) {
        int hcl = t * 8 + 2 * qq;
        int m   = wid * 16 + rr;
        stg[(size_t)m * PSTG + hcl]           = sacc[t][0];
        stg[(size_t)m * PSTG + hcl + 1]       = sacc[t][1];
        stg[(size_t)(m + 8) * PSTG + hcl]     = sacc[t][2];
        stg[(size_t)(m + 8) * PSTG + hcl + 1] = sacc[t][3];
    }
    __syncthreads();

#pragma unroll
    for (int it = 0; it < 16; it++) {
        int f = it * 256 + tid;
        int m = f >> 5, c4 = (f & 31) << 2;
        const float* s = stg + (size_t)m * PSTG + c4;
        uint32_t h01, l01, h23, l23;
        split2(s[0], s[1], h01, l01);
        split2(s[2], s[3], h23, l23);
        size_t base = ((size_t)b * MDIM + m) * HDIM + h0 + c4;
        *(uint2*)(g_WpT_hi + base) = make_uint2(h01, h23);
        *(uint2*)(g_WpT_lo + base) = make_uint2(l01, l23);
    }
#pragma unroll
    for (int it = 0; it < 16; it++) {
        int f = it * 256 + tid;
        int h = f >> 5, m4 = (f & 31) << 2;
        float x0 = stg[(size_t)(m4 + 0) * PSTG + h];
        float x1 = stg[(size_t)(m4 + 1) * PSTG + h];
        float x2 = stg[(size_t)(m4 + 2) * PSTG + h];
        float x3 = stg[(size_t)(m4 + 3) * PSTG + h];
        uint32_t p01 = packh2(x0, x1), p23 = packh2(x2, x3);
        size_t base = ((size_t)b * HDIM + h0 + h) * MDIM + m4;
        *(uint2*)(g_Wp_f16 + base) = make_uint2(p01, p23);
    }
}

// ============================================================
// Kernel 2: GEMM1 now warp m-split (warp w owns all 64 n x m slice
// [32w,32w+32)) -> each warp loads the full Q tile but only 1/4 of
// the K tile: GEMM1 LDSM down 33%. Softmax does a cross-warp
// m-reduction through smem; E round-trips smem as fp16 (lossless)
// and GEMM2 reloads it in n-split layout via ldsm. GEMM2 unchanged.
// 4 CTAs/SM, numerics bit-identical to R13.
//
// SMEM union (bytes):
//   GEMM1: KB0 @0 (20480), KB1 @20480 (end 40960), Q @40960 (9216) -> 50176
//   softmax scratch: pm @34816 (1KB), ps @35840 (1KB)  [dead STG area]
//   E tile @34816 (64 x 136 fp16 = 17408) after reductions
//   GEMM2: WB0 @0 (17408), WB1 @17408 (end 34816), STG @34816 (17408)
//   recip @52224 (256)                                   -> 52480 total
// ============================================================
#define PADQ 72
#define PADK 40
#define PADW 136
#define PADE 136     // E tile fp16 row stride (272 B)
#define STGS 68
#define OFF_KB  0
#define KB_SZ   20480
#define OFF_Q   40960
#define OFF_WB  0
#define WB_SZ   17408
#define OFF_E   34816
#define OFF_STG 34816
#define OFF_RCP 52224
#define SMEM_DYN 52480

__global__ __launch_bounds__(128, 4)
void attn_kernel(const float* __restrict__ H, float* __restrict__ out) {
    extern __shared__ char smem[];
    const uint32_t sbase = smem_u32(smem);

    const int tid = threadIdx.x;
    const int wid = tid >> 5;
    const int lid = tid & 31;
    const int b   = blockIdx.y;
    const int n0  = blockIdx.x * 64;

    const float* Hb = H + (size_t)b * HDIM * NDIM + n0;
    const __nv_bfloat16* KTh = g_WpT_hi + (size_t)b * MDIM * HDIM;
    const __nv_bfloat16* KTl = g_WpT_lo + (size_t)b * MDIM * HDIM;
    const __half*        Wpf = g_Wp_f16 + (size_t)b * HDIM * MDIM;

    const int g  = lid >> 3, lr = lid & 7;
    const int rr = lid >> 2, qq = lid & 3;
    // GEMM1 A (trans ldsm from [k][n]): rows k, cols n (per-nt offset added)
    const int arow_k = ((g & 2) ? 8 : 0) + lr;
    const int acq    = (g & 1) ? 8 : 0;
    // GEMM1/GEMM2 B (non-trans ldsm): rows = tile rows, col halves by k
    const int brow_m = ((g >> 1) ? 8 : 0) + lr;
    const int bcq    = (g & 1) ? 8 : 0;
    const uint32_t b_off_w = (uint32_t)(brow_m * PADW + bcq) * 2;
    // GEMM2 A (E, non-trans ldsm from [n][k]): rows n, col halves by k
    const int earow = ((g & 1) ? 8 : 0) + lr;
    const uint32_t e_off = (uint32_t)((16 * wid + earow) * (PADE * 2) + ((g & 2) ? 16 : 0));

    auto issue_k = [&](int hc, int p) {
        uint32_t dh = sbase + OFF_KB + p * KB_SZ;
        uint32_t dl = dh + 10240;
        int k0 = hc * 32;
#pragma unroll
        for (int it = 0; it < 4; it++) {
            int f = it * 128 + tid, m = f >> 2, c8 = (f & 3) << 3;
            uint32_t o = (uint32_t)(m * PADK + c8) * 2;
            CP_ASYNC16(dh + o, KTh + (size_t)m * HDIM + k0 + c8);
            CP_ASYNC16(dl + o, KTl + (size_t)m * HDIM + k0 + c8);
        }
    };
    auto issue_w = [&](int hc2, int p) {
        uint32_t dw = sbase + OFF_WB + p * WB_SZ;
#pragma unroll
        for (int it = 0; it < 8; it++) {
            int f = it * 128 + tid, hr = f >> 4, c8 = (f & 15) << 3;
            uint32_t o = (uint32_t)(hr * PADW + c8) * 2;
            CP_ASYNC16(dw + o, Wpf + (size_t)(hc2 * 64 + hr) * MDIM + c8);
        }
    };
    auto ldg_q = [&](int hc, float4* qv) {
#pragma unroll
        for (int it = 0; it < 4; it++) {
            int f = it * 128 + tid, hr = f >> 4, c4 = (f & 15) << 2;
            qv[it] = *(const float4*)(Hb + (size_t)(hc * 32 + hr) * NDIM + c4);
        }
    };
    auto conv_q = [&](const float4* qv) {
#pragma unroll
        for (int it = 0; it < 4; it++) {
            int f = it * 128 + tid, hr = f >> 4, c4 = (f & 15) << 2;
            uint32_t h01, l01, h23, l23;
            split2(qv[it].x, qv[it].y, h01, l01);
            split2(qv[it].z, qv[it].w, h23, l23);
            uint32_t off = (uint32_t)(hr * PADQ + c4) * 2;
            *(uint2*)(smem + OFF_Q + off)        = make_uint2(h01, h23);
            *(uint2*)(smem + OFF_Q + 4608 + off) = make_uint2(l01, l23);
        }
    };

    // ------ GEMM1 (m-split): sacc[nt*4+u], u = mt*2+c ------
    // n = nt*16 + rr (+8 for j>=2); m = 32*wid + (u>>1)*16 + (u&1)*8 + 2qq + (j&1)
    float sacc[16][4];
#pragma unroll
    for (int t = 0; t < 16; t++)
#pragma unroll
        for (int j = 0; j < 4; j++) sacc[t][j] = 0.f;

    float4 qv[4];
    issue_k(0, 0); CP_COMMIT();
    ldg_q(0, qv);
    conv_q(qv);
    ldg_q(1, qv);

    const uint32_t qhi = sbase + OFF_Q;
    const uint32_t qlo = qhi + 4608;

    for (int hc = 0; hc < 16; hc++) {
        const int p = hc & 1;
        CP_WAIT(0);
        __syncthreads();
        if (hc < 15) { issue_k(hc + 1, p ^ 1); CP_COMMIT(); }

        const uint32_t khi = sbase + OFF_KB + p * KB_SZ;
        const uint32_t klo = khi + 10240;
#pragma unroll
        for (int kk = 0; kk < 2; kk++) {
            // B: this warp's m32 slice (2 m16-tiles), hi+lo
            uint32_t bh0[4], bl0[4], bh1[4], bl1[4];
            uint32_t bo0 = (uint32_t)((32 * wid + brow_m) * PADK + bcq + kk * 16) * 2;
            uint32_t bo1 = bo0 + (uint32_t)(16 * PADK) * 2;
            ldsm4(bh0, khi + bo0);
            ldsm4(bh1, khi + bo1);
            ldsm4(bl0, klo + bo0);
            ldsm4(bl1, klo + bo1);
#pragma unroll
            for (int nt = 0; nt < 4; nt++) {
                uint32_t ah[4], al[4];
                uint32_t ao = (uint32_t)((arow_k + kk * 16) * PADQ + nt * 16 + acq) * 2;
                ldsm4t(ah, qhi + ao);
                ldsm4t(al, qlo + ao);
                float* A0 = sacc[nt * 4 + 0];
                float* A1 = sacc[nt * 4 + 1];
                float* A2 = sacc[nt * 4 + 2];
                float* A3 = sacc[nt * 4 + 3];
                mma16816(A0, ah, bh0[0], bh0[1]);
                mma16816(A1, ah, bh0[2], bh0[3]);
                mma16816(A2, ah, bh1[0], bh1[1]);
                mma16816(A3, ah, bh1[2], bh1[3]);
                mma16816(A0, ah, bl0[0], bl0[1]);
                mma16816(A1, ah, bl0[2], bl0[3]);
                mma16816(A2, ah, bl1[0], bl1[1]);
                mma16816(A3, ah, bl1[2], bl1[3]);
                mma16816(A0, al, bh0[0], bh0[1]);
                mma16816(A1, al, bh0[2], bh0[3]);
                mma16816(A2, al, bh1[0], bh1[1]);
                mma16816(A3, al, bh1[2], bh1[3]);
            }
        }
        __syncthreads();
        if (hc < 15) conv_q(qv);
        if (hc < 14) ldg_q(hc + 2, qv);
    }

    // prefetch GEMM2 chunk 0 (WB0 aliases dead KB0)
    issue_w(0, 0); CP_COMMIT();

    // ---------------- softmax over m (cross-warp m-reduction) ----------------
    float* pm = (float*)(smem + OFF_E);          // [4 warps][64 n]
    float* ps = (float*)(smem + OFF_E + 1024);   // [4 warps][64 n]
    float* rcp = (float*)(smem + OFF_RCP);       // [64 n]

    float mx[4][2];
#pragma unroll
    for (int nt = 0; nt < 4; nt++) { mx[nt][0] = -3.4e38f; mx[nt][1] = -3.4e38f; }
#pragma unroll
    for (int t = 0; t < 16; t++) {
        int nt = t >> 2;
        mx[nt][0] = fmaxf(mx[nt][0], fmaxf(sacc[t][0], sacc[t][1]));
        mx[nt][1] = fmaxf(mx[nt][1], fmaxf(sacc[t][2], sacc[t][3]));
    }
#pragma unroll
    for (int nt = 0; nt < 4; nt++)
#pragma unroll
        for (int hf = 0; hf < 2; hf++) {
            mx[nt][hf] = fmaxf(mx[nt][hf], __shfl_xor_sync(0xFFFFFFFFu, mx[nt][hf], 1));
            mx[nt][hf] = fmaxf(mx[nt][hf], __shfl_xor_sync(0xFFFFFFFFu, mx[nt][hf], 2));
        }
    if (qq == 0) {
#pragma unroll
        for (int nt = 0; nt < 4; nt++)
#pragma unroll
            for (int hf = 0; hf < 2; hf++)
                pm[wid * 64 + nt * 16 + hf * 8 + rr] = mx[nt][hf];
    }
    __syncthreads();
    float rmax[4][2];
#pragma unroll
    for (int nt = 0; nt < 4; nt++)
#pragma unroll
        for (int hf = 0; hf < 2; hf++) {
            int n = nt * 16 + hf * 8 + rr;
            float v = fmaxf(pm[n], pm[64 + n]);
            v = fmaxf(v, fmaxf(pm[128 + n], pm[192 + n]));
            rmax[nt][hf] = v;
        }
    float sm[4][2];
#pragma unroll
    for (int nt = 0; nt < 4; nt++) { sm[nt][0] = 0.f; sm[nt][1] = 0.f; }
#pragma unroll
    for (int t = 0; t < 16; t++) {
        int nt = t >> 2;
        sacc[t][0] = __expf(sacc[t][0] - rmax[nt][0]);
        sacc[t][1] = __expf(sacc[t][1] - rmax[nt][0]);
        sacc[t][2] = __expf(sacc[t][2] - rmax[nt][1]);
        sacc[t][3] = __expf(sacc[t][3] - rmax[nt][1]);
        sm[nt][0] += sacc[t][0] + sacc[t][1];
        sm[nt][1] += sacc[t][2] + sacc[t][3];
    }
#pragma unroll
    for (int nt = 0; nt < 4; nt++)
#pragma unroll
        for (int hf = 0; hf < 2; hf++) {
            sm[nt][hf] += __shfl_xor_sync(0xFFFFFFFFu, sm[nt][hf], 1);
            sm[nt][hf] += __shfl_xor_sync(0xFFFFFFFFu, sm[nt][hf], 2);
        }
    if (qq == 0) {
#pragma unroll
        for (int nt = 0; nt < 4; nt++)
#pragma unroll
            for (int hf = 0; hf < 2; hf++)
                ps[wid * 64 + nt * 16 + hf * 8 + rr] = sm[nt][hf];
    }
    __syncthreads();
    if (wid == 0 && qq == 0) {
#pragma unroll
        for (int nt = 0; nt < 4; nt++)
#pragma unroll
            for (int hf = 0; hf < 2; hf++) {
                int n = nt * 16 + hf * 8 + rr;
                rcp[n] = 1.0f / (ps[n] + ps[64 + n] + ps[128 + n] + ps[192 + n]);
            }
    }
    __syncthreads();   // all ps/pm reads done; E may overwrite the area

    // ---- write unnormalized E (fp16) to smem [n64][m128], stride PADE ----
#pragma unroll
    for (int t = 0; t < 16; t++) {
        int nt = t >> 2, u = t & 3;
        int m  = 32 * wid + (u >> 1) * 16 + (u & 1) * 8 + 2 * qq;
        int nr = nt * 16 + rr;
        *(uint32_t*)(smem + OFF_E + (size_t)nr * (PADE * 2) + m * 2) =
            packh2(sacc[t][0], sacc[t][1]);
        *(uint32_t*)(smem + OFF_E + (size_t)(nr + 8) * (PADE * 2) + m * 2) =
            packh2(sacc[t][2], sacc[t][3]);
    }
    __syncthreads();

    // ---- reload E as GEMM2 A-fragments (n-split: warp w owns n16 slice) ----
    uint32_t ef[8][4];
#pragma unroll
    for (int kk = 0; kk < 8; kk++)
        ldsm4(ef[kk], sbase + OFF_E + e_off + kk * 32);
    const float r0 = ((float*)(smem + OFF_RCP))[16 * wid + rr];
    const float r1 = ((float*)(smem + OFF_RCP))[16 * wid + rr + 8];

    // -------- GEMM2: C[n][h] = sum_m E[n][m] * Wp[h][m], fp16 x fp16 --------
    float* outb = out + (size_t)b * HDIM * NDIM;
    float* stg = (float*)(smem + OFF_STG);

    for (int hc2 = 0; hc2 < 8; hc2++) {
        const int p = hc2 & 1;
        CP_WAIT(0);
        __syncthreads();                 // WB[p] visible; STG free (ef loaded)
        if (hc2 < 7) { issue_w(hc2 + 1, p ^ 1); CP_COMMIT(); }

        float cacc[8][4];
#pragma unroll
        for (int t = 0; t < 8; t++)
#pragma unroll
            for (int j = 0; j < 4; j++) cacc[t][j] = 0.f;

        const uint32_t wb = sbase + OFF_WB + p * WB_SZ;
#pragma unroll
        for (int kk = 0; kk < 8; kk++) {
            uint32_t b0[4], b1[4], b2[4], b3[4];
            uint32_t ko = (uint32_t)(kk * 16) * 2;
            ldsm4(b0, wb + b_off_w + ko);
            ldsm4(b1, wb + b_off_w + (uint32_t)(16 * PADW) * 2 + ko);
            ldsm4(b2, wb + b_off_w + (uint32_t)(32 * PADW) * 2 + ko);
            ldsm4(b3, wb + b_off_w + (uint32_t)(48 * PADW) * 2 + ko);
            mma16816f(cacc[0], ef[kk], b0[0], b0[1]);
            mma16816f(cacc[1], ef[kk], b0[2], b0[3]);
            mma16816f(cacc[2], ef[kk], b1[0], b1[1]);
            mma16816f(cacc[3], ef[kk], b1[2], b1[3]);
            mma16816f(cacc[4], ef[kk], b2[0], b2[1]);
            mma16816f(cacc[5], ef[kk], b2[2], b2[3]);
            mma16816f(cacc[6], ef[kk], b3[0], b3[1]);
            mma16816f(cacc[7], ef[kk], b3[2], b3[3]);
        }

        // scale by 1/sum and stage transposed: stg[h_local][n]
#pragma unroll
        for (int t = 0; t < 8; t++) {
            int hcl = t * 8 + 2 * qq;
            int n   = wid * 16 + rr;
            stg[(size_t)hcl * STGS + n]           = cacc[t][0] * r0;
            stg[(size_t)(hcl + 1) * STGS + n]     = cacc[t][1] * r0;
            stg[(size_t)hcl * STGS + n + 8]       = cacc[t][2] * r1;
            stg[(size_t)(hcl + 1) * STGS + n + 8] = cacc[t][3] * r1;
        }
        __syncthreads();                 // stage writes visible

        // coalesced fp32 store: out[b][hc2*64+hr][n0 + ...]
#pragma unroll
        for (int it = 0; it < 8; it++) {
            int f = it * 128 + tid, hr = f >> 4, n4 = (f & 15) << 2;
            float4 v = *(const float4*)(stg + (size_t)hr * STGS + n4);
            *(float4*)(outb + (size_t)(hc2 * 64 + hr) * NDIM + n0 + n4) = v;
        }
        // STG reuse protected by the next chunk's top __syncthreads()
    }
}

// ============================================================
extern "C" void kernel_launch(void* const* d_in, const int* in_sizes, int n_in,
                              void* d_out, int out_size) {
    const float* H      = (const float*)d_in[0];  // [32,512,64,64]
    const float* W      = (const float*)d_in[1];  // [32,256,128]
    const float* head_w = (const float*)d_in[2];  // [512,256]
    float* out = (float*)d_out;

    cudaFuncSetAttribute(proj_kernel,
                         cudaFuncAttributeMaxDynamicSharedMemorySize, PSMEM);
    cudaFuncSetAttribute(attn_kernel,
                         cudaFuncAttributeMaxDynamicSharedMemorySize, SMEM_DYN);

    proj_kernel<<<dim3(4, B_DIM), 256, PSMEM>>>(W, head_w);
    attn_kernel<<<dim3(NDIM / 64, B_DIM), 128, SMEM_DYN>>>(H, out);
}